// round 14
// baseline (speedup 1.0000x reference)
#include <cuda_runtime.h>
#include <cuda_fp16.h>
#include <math.h>
#include <stdint.h>

#define HID 256
#define CND 128
#define KCL 16
#define PH  8
#define NMAX 262144
#define BMAX 2048

// ---------------- scratch (static device allocations) --------------------
__device__ float d_S [(size_t)NMAX * KCL];       // softmax * alpha (folded)
__device__ float d_cluster[(size_t)BMAX * KCL * HID];
__device__ int   d_seg[BMAX + 1];
__device__ float d_u  [HID * PH];
__device__ float d_Qm [HID * PH];
__device__ float d_bq [PH];
__device__ float d_Wcv[HID * HID];
__device__ float d_bv [HID];
// single-fp16 transposed weights (K-major [N rows][K cols], rn-rounded)
__device__ __half d_w1t[256 * 384];
__device__ __half d_a1t[256 * 256];

__device__ __forceinline__ float geluf(float x) {
    return 0.5f * x * (1.0f + erff(x * 0.7071067811865475f));
}
__device__ __forceinline__ uint32_t smem_u32(const void* p) {
    uint32_t a;
    asm("{ .reg .u64 t; cvta.to.shared.u64 t, %1; cvt.u32.u64 %0, t; }"
        : "=r"(a) : "l"(p));
    return a;
}

#define SW128(o) ((o) ^ (((o) >> 3) & 0x70))

#define LDSM_X4(r, addr) \
    asm volatile("ldmatrix.sync.aligned.m8n8.x4.shared.b16 {%0,%1,%2,%3}, [%4];" \
        : "=r"((r)[0]), "=r"((r)[1]), "=r"((r)[2]), "=r"((r)[3]) : "r"(addr))
#define MMA16816F(c, a, b) \
    asm volatile("mma.sync.aligned.m16n8k16.row.col.f32.f16.f16.f32 " \
        "{%0,%1,%2,%3}, {%4,%5,%6,%7}, {%8,%9}, {%0,%1,%2,%3};" \
        : "+f"((c)[0]), "+f"((c)[1]), "+f"((c)[2]), "+f"((c)[3]) \
        : "r"((a)[0]), "r"((a)[1]), "r"((a)[2]), "r"((a)[3]), \
          "r"((b)[0]), "r"((b)[1]))
#define CP_A16(dst, src) \
    asm volatile("cp.async.cg.shared.global [%0], [%1], 16;" \
        :: "r"(dst), "l"(src) : "memory")
#define CP_A16Z(dst, src, sz) \
    asm volatile("cp.async.cg.shared.global [%0], [%1], 16, %2;" \
        :: "r"(dst), "l"(src), "r"(sz) : "memory")
#define CP_COMMIT() asm volatile("cp.async.commit_group;" ::: "memory")
#define CP_WAIT0()  asm volatile("cp.async.wait_group 0;" ::: "memory")

// smem byte layout per CTA (64-row tile; 2 CTAs/SM)
#define S_BIAS1 0        // 256 f32
#define S_W2    1024     // 256 f32
#define S_AB1   2048     // 256 f32
#define S_AB2   3072     // 16 f32
#define S_ALPHA 3200     // 64 f32
#define S_REDG  3456     // 64 f32
#define S_RED2  3712     // 64*16 f32 = 4096 (ends 7808)
#define AST     8192     // 16KB f32 A staging (aliased as A2 table in epi2)
#define ABF     24576    // 16KB fp16 A (hi @+0, lo @+8192), 64 rows x 128B
#define BB0     40960    // 32KB fp16 B buf0, 256 rows x 128B
#define BB1     73728    // 32KB fp16 B buf1
#define SMEMSZ  106496

// ---------------- tiny prep kernels --------------------------------------
__global__ void k_cvtw1(const float* __restrict__ W) {
    int t = blockIdx.x, j = threadIdx.x;            // W[384][256] -> WT[256][384]
    d_w1t[(size_t)j * 384 + t] = __float2half_rn(W[(size_t)t * 256 + j]);
}
__global__ void k_cvta1(const float* __restrict__ A) {
    int t = blockIdx.x, j = threadIdx.x;
    d_a1t[(size_t)j * 256 + t] = __float2half_rn(A[(size_t)t * 256 + j]);
}

// ---------------- K0: segment starts -------------------------------------
__global__ void k_seg(const int* __restrict__ batch, int N, int B) {
    int n = blockIdx.x * blockDim.x + threadIdx.x;
    if (n >= N) return;
    int bn = batch[n];
    if (n == 0) {
        for (int b = 0; b <= bn; b++) d_seg[b] = 0;
    } else {
        int bp = batch[n - 1];
        if (bn != bp) for (int b = bp + 1; b <= bn; b++) d_seg[b] = n;
    }
    if (n == N - 1) {
        for (int b = bn + 1; b <= B; b++) d_seg[b] = N;
    }
}

// ---------------- readout prep (parallel) --------------------------------
__global__ void k_u2(const float* __restrict__ Wk, const float* __restrict__ q) {
    __shared__ float qs[HID];
    int tid = threadIdx.x, t = blockIdx.x;
    qs[tid] = q[tid];
    __syncthreads();
    int lane = tid & 31, p = tid >> 5;
    float v = Wk[(size_t)t * HID + tid] * qs[tid];
    #pragma unroll
    for (int off = 16; off; off >>= 1)
        v += __shfl_xor_sync(0xffffffffu, v, off);
    if (lane == 0) d_u[t * PH + p] = v;
}
__global__ __launch_bounds__(256) void k_wcv(
    const float* __restrict__ Wc, const float* __restrict__ Wv,
    const float* __restrict__ bc) {
    int i = blockIdx.x, j = threadIdx.x;
    float a = 0.f;
    if (i < HID) {
        #pragma unroll 4
        for (int t = 0; t < HID; t++)
            a += Wc[(size_t)i * HID + t] * Wv[(size_t)t * HID + j];
        d_Wcv[(size_t)i * HID + j] = a;
    } else {
        #pragma unroll 4
        for (int t = 0; t < HID; t++)
            a += bc[t] * Wv[(size_t)t * HID + j];
        d_bv[j] = a;
    }
}
__global__ __launch_bounds__(256) void k_qm(
    const float* __restrict__ Wc, const float* __restrict__ bc) {
    __shared__ float wrow[HID];
    int i = blockIdx.x, tid = threadIdx.x;
    wrow[tid] = (i < HID) ? Wc[(size_t)i * HID + tid] : bc[tid];
    __syncthreads();
    int p = tid >> 5, lane = tid & 31;
    float v = 0.f;
    #pragma unroll
    for (int t = 0; t < 8; t++) {
        int idx = lane + 32 * t;
        v += wrow[idx] * d_u[idx * PH + p];
    }
    #pragma unroll
    for (int off = 16; off; off >>= 1)
        v += __shfl_xor_sync(0xffffffffu, v, off);
    if (lane == 0) { if (i < HID) d_Qm[i * PH + p] = v; else d_bq[p] = v; }
}

// ======================= fused atom kernel (fp16) =========================
template <int TWO_PASS>
__device__ __forceinline__ void mma_block(uint32_t abf, uint32_t bbase,
                                          int lane, int wm, int wn,
                                          float acc[2][8][4]) {
    #pragma unroll
    for (int ks = 0; ks < 4; ks++) {
        int kb = ks * 32;
        uint32_t ah[2][4], al[2][4];
        #pragma unroll
        for (int mt = 0; mt < 2; mt++) {
            int mb = wm * 32 + mt * 16 + (lane & 7) + ((lane & 8) ? 8 : 0);
            uint32_t ao = SW128((uint32_t)(mb * 128 + kb + ((lane & 16) ? 16 : 0)));
            LDSM_X4(ah[mt], abf + ao);
            if (TWO_PASS) LDSM_X4(al[mt], abf + 8192 + ao);
        }
        #pragma unroll
        for (int np = 0; np < 4; np++) {
            int nb = wn * 64 + (np * 2 + ((lane >> 4) & 1)) * 8 + (lane & 7);
            uint32_t bo = SW128((uint32_t)(nb * 128 + kb + ((lane & 8) ? 16 : 0)));
            uint32_t bh[4];
            LDSM_X4(bh, bbase + bo);
            MMA16816F(acc[0][2*np],   ah[0], bh);
            MMA16816F(acc[1][2*np],   ah[1], bh);
            MMA16816F(acc[0][2*np+1], ah[0], bh + 2);
            MMA16816F(acc[1][2*np+1], ah[1], bh + 2);
            if (TWO_PASS) {
                MMA16816F(acc[0][2*np],   al[0], bh);
                MMA16816F(acc[1][2*np],   al[1], bh);
                MMA16816F(acc[0][2*np+1], al[0], bh + 2);
                MMA16816F(acc[1][2*np+1], al[1], bh + 2);
            }
        }
    }
}

__global__ void __launch_bounds__(256, 2) k_fused(
    const float* __restrict__ h, const float* __restrict__ c,
    const float* __restrict__ b1, const float* __restrict__ W2,
    const float* __restrict__ b2, const float* __restrict__ ab1,
    const float* __restrict__ A2, const float* __restrict__ ab2, int N) {
    extern __shared__ __align__(1024) char smem[];
    uint32_t sb = smem_u32(smem);
    int tid = threadIdx.x, lane = tid & 31, wid = tid >> 5;
    int wm = wid & 1, wn = wid >> 1;     // 2 x 4 warp grid: 64 rows x 256 cols
    int r0 = blockIdx.x * 64;

    float* bias1 = (float*)(smem + S_BIAS1);
    float* w2s   = (float*)(smem + S_W2);
    float* ab1s  = (float*)(smem + S_AB1);
    float* ab2s  = (float*)(smem + S_AB2);
    float* alpha = (float*)(smem + S_ALPHA);
    float* redg  = (float*)(smem + S_REDG);
    float* red2  = (float*)(smem + S_RED2);

    bias1[tid] = b1[tid];
    w2s[tid]   = W2[tid];
    ab1s[tid]  = ab1[tid];
    if (tid < 16) ab2s[tid] = ab2[tid];
    if (tid < 64) { redg[tid] = 0.f; alpha[tid] = 0.f; }
    for (int i = tid; i < 64 * 16; i += 256) red2[i] = 0.f;

    // per-thread load coordinates
    int a_row = tid >> 4, a_c4 = (tid & 15) * 4;   // A: 16 rows/pass, 4 passes
    int b_row = tid >> 3, b_u8 = (tid & 7) * 8;    // B: 32 rows/pass, 8 passes

    // A source: phase 1 reads [h|c] chunk; phase 2 reads h chunk (alpha folded out)
    auto issueA = [&](const float* src1, int ch) {
        int kt = ch * 64;
        const float* src; int stride, cb;
        if (kt < 256) { src = src1; stride = 256; cb = kt; }
        else          { src = c;    stride = 128; cb = kt - 256; }
        #pragma unroll
        for (int i = 0; i < 4; i++) {
            int idx = tid + i * 256;
            int row = a_row + i * 16;
            int gr = r0 + row;
            const float* sp = src + (size_t)gr * stride + cb + a_c4;
            int sz = (gr < N) ? 16 : 0;
            CP_A16Z(sb + AST + idx * 16, sp, sz);
        }
    };
    auto issueB = [&](const __half* Bt, int stride, int ch, uint32_t bbuf) {
        int kt = ch * 64;
        #pragma unroll
        for (int i = 0; i < 8; i++) {
            int row = b_row + i * 32;
            uint32_t off = SW128((uint32_t)(row * 128 + b_u8 * 2));
            CP_A16(sb + bbuf + off, Bt + (size_t)row * stride + kt + b_u8);
        }
    };

    float acc[2][8][4];
    #pragma unroll
    for (int a = 0; a < 2; a++)
        #pragma unroll
        for (int b = 0; b < 8; b++)
            #pragma unroll
            for (int e = 0; e < 4; e++) acc[a][b][e] = 0.f;

    // =================== phase 1: D1 = [h|c] @ W1  (1-pass) ==============
    issueA(h, 0);
    issueB(d_w1t, 384, 0, BB0);
    CP_COMMIT();
    for (int ch = 0; ch < 6; ch++) {
        uint32_t bbuf = (ch & 1) ? BB1 : BB0;
        CP_WAIT0();
        __syncthreads();
        // splitA, hi only
        #pragma unroll
        for (int i = 0; i < 4; i++) {
            int idx = tid + i * 256;
            int row = a_row + i * 16;
            float4 v = *(const float4*)(smem + AST + idx * 16);
            __half h0 = __float2half_rn(v.x), h1 = __float2half_rn(v.y);
            __half h2 = __float2half_rn(v.z), h3 = __float2half_rn(v.w);
            uint32_t off = SW128((uint32_t)(row * 128 + a_c4 * 2));
            uint2 ph_ = make_uint2(
                (uint32_t)__half_as_ushort(h0) | ((uint32_t)__half_as_ushort(h1) << 16),
                (uint32_t)__half_as_ushort(h2) | ((uint32_t)__half_as_ushort(h3) << 16));
            *(uint2*)(smem + ABF + off) = ph_;
        }
        if (ch < 5) {
            issueA(h, ch + 1);
            issueB(d_w1t, 384, ch + 1, (ch & 1) ? BB0 : BB1);
        } else {
            // phase-2 chunk0 prefetch: A = h (alpha-independent!) + A1 B tile
            issueA(h, 0);
            issueB(d_a1t, 256, 0, BB0);
        }
        CP_COMMIT();
        __syncthreads();
        mma_block<0>(sb + ABF, sb + bbuf, lane, wm, wn, acc);
    }
    // =================== epilogue 1: gate -> alpha (no hg write) =========
    #pragma unroll
    for (int mt = 0; mt < 2; mt++) {
        float s0 = 0.f, s1 = 0.f;
        #pragma unroll
        for (int nt = 0; nt < 8; nt++) {
            int n = wn * 64 + nt * 8 + (lane & 3) * 2;
            float b0v = bias1[n], b1v = bias1[n + 1];
            float w0 = w2s[n], w1v = w2s[n + 1];
            s0 += geluf(acc[mt][nt][0] + b0v) * w0 + geluf(acc[mt][nt][1] + b1v) * w1v;
            s1 += geluf(acc[mt][nt][2] + b0v) * w0 + geluf(acc[mt][nt][3] + b1v) * w1v;
        }
        s0 += __shfl_xor_sync(0xffffffffu, s0, 1);
        s0 += __shfl_xor_sync(0xffffffffu, s0, 2);
        s1 += __shfl_xor_sync(0xffffffffu, s1, 1);
        s1 += __shfl_xor_sync(0xffffffffu, s1, 2);
        if ((lane & 3) == 0) {
            int r = wm * 32 + mt * 16 + (lane >> 2);
            atomicAdd(&redg[r], s0);
            atomicAdd(&redg[r + 8], s1);
        }
    }
    __syncthreads();
    if (tid < 64) alpha[tid] = 1.f / (1.f + expf(-(redg[tid] + b2[0])));
    // =================== phase 2: E = h @ A1  (2-pass) ===================
    #pragma unroll
    for (int a = 0; a < 2; a++)
        #pragma unroll
        for (int b = 0; b < 8; b++)
            #pragma unroll
            for (int e = 0; e < 4; e++) acc[a][b][e] = 0.f;

    for (int ch = 0; ch < 4; ch++) {
        uint32_t bbuf = (ch & 1) ? BB1 : BB0;
        CP_WAIT0();
        __syncthreads();
        // splitA, hi + lo
        #pragma unroll
        for (int i = 0; i < 4; i++) {
            int idx = tid + i * 256;
            int row = a_row + i * 16;
            float4 v = *(const float4*)(smem + AST + idx * 16);
            __half h0 = __float2half_rn(v.x), h1 = __float2half_rn(v.y);
            __half h2 = __float2half_rn(v.z), h3 = __float2half_rn(v.w);
            __half l0 = __float2half_rn(v.x - __half2float(h0));
            __half l1 = __float2half_rn(v.y - __half2float(h1));
            __half l2 = __float2half_rn(v.z - __half2float(h2));
            __half l3 = __float2half_rn(v.w - __half2float(h3));
            uint32_t off = SW128((uint32_t)(row * 128 + a_c4 * 2));
            uint2 ph_ = make_uint2(
                (uint32_t)__half_as_ushort(h0) | ((uint32_t)__half_as_ushort(h1) << 16),
                (uint32_t)__half_as_ushort(h2) | ((uint32_t)__half_as_ushort(h3) << 16));
            uint2 pl_ = make_uint2(
                (uint32_t)__half_as_ushort(l0) | ((uint32_t)__half_as_ushort(l1) << 16),
                (uint32_t)__half_as_ushort(l2) | ((uint32_t)__half_as_ushort(l3) << 16));
            *(uint2*)(smem + ABF + off) = ph_;
            *(uint2*)(smem + ABF + 8192 + off) = pl_;
        }
        if (ch < 3) {
            issueA(h, ch + 1);
            issueB(d_a1t, 256, ch + 1, (ch & 1) ? BB0 : BB1);
        }
        CP_COMMIT();
        __syncthreads();
        mma_block<1>(sb + ABF, sb + bbuf, lane, wm, wn, acc);
    }
    // load A2 table into AST region (free after last splitA)
    {
        float* a2s = (float*)(smem + AST);
        for (int i = tid; i < 256 * 16; i += 256) a2s[i] = A2[i];
    }
    __syncthreads();
    // ============ epilogue 2: alpha-scale + @A2 + softmax*alpha -> d_S ===
    {
        const float* a2s = (const float*)(smem + AST);
        #pragma unroll
        for (int mt = 0; mt < 2; mt++) {
            float l0[16], l1[16];
            #pragma unroll
            for (int k = 0; k < 16; k++) { l0[k] = 0.f; l1[k] = 0.f; }
            float ar0 = alpha[wm * 32 + mt * 16 + (lane >> 2)];
            float ar1 = alpha[wm * 32 + mt * 16 + (lane >> 2) + 8];
            #pragma unroll
            for (int nt = 0; nt < 8; nt++) {
                int n = wn * 64 + nt * 8 + (lane & 3) * 2;
                #pragma unroll
                for (int e = 0; e < 4; e++) {
                    int col = n + (e & 1);
                    float av = (e < 2) ? ar0 : ar1;
                    float v = geluf(av * acc[mt][nt][e] + ab1s[col]);
                    const float* ar = &a2s[col * 16];
                    float* dst = (e < 2) ? l0 : l1;
                    #pragma unroll
                    for (int k = 0; k < 16; k++) dst[k] += v * ar[k];
                }
            }
            #pragma unroll
            for (int k = 0; k < 16; k++) {
                l0[k] += __shfl_xor_sync(0xffffffffu, l0[k], 1);
                l0[k] += __shfl_xor_sync(0xffffffffu, l0[k], 2);
                l1[k] += __shfl_xor_sync(0xffffffffu, l1[k], 1);
                l1[k] += __shfl_xor_sync(0xffffffffu, l1[k], 2);
            }
            if ((lane & 3) == 0) {
                int r = wm * 32 + mt * 16 + (lane >> 2);
                #pragma unroll
                for (int k = 0; k < 16; k++) {
                    atomicAdd(&red2[r * 16 + k], l0[k]);
                    atomicAdd(&red2[(r + 8) * 16 + k], l1[k]);
                }
            }
        }
    }
    __syncthreads();
    if (tid < 64) {
        int gr = r0 + tid;
        if (gr < N) {
            float l[16], mx = -1e30f;
            #pragma unroll
            for (int k = 0; k < 16; k++) {
                l[k] = red2[tid * 16 + k] + ab2s[k];
                mx = fmaxf(mx, l[k]);
            }
            float s = 0.f;
            #pragma unroll
            for (int k = 0; k < 16; k++) { l[k] = expf(l[k] - mx); s += l[k]; }
            float inv = alpha[tid] / s;          // fold alpha into S
            #pragma unroll
            for (int k4 = 0; k4 < 4; k4++) {
                float4 o = make_float4(l[4*k4] * inv, l[4*k4+1] * inv,
                                       l[4*k4+2] * inv, l[4*k4+3] * inv);
                *(float4*)(d_S + (size_t)gr * 16 + 4 * k4) = o;
            }
        }
    }
}

// ---------------- K3: segment pool (S includes alpha; pools raw h) -------
__global__ __launch_bounds__(256) void k_pool(const float* __restrict__ h) {
    int b = blockIdx.x, tid = threadIdx.x;
    int s = d_seg[b], e = d_seg[b + 1];
    float acc[16];
    #pragma unroll
    for (int k = 0; k < 16; k++) acc[k] = 0.f;
    __shared__ __align__(16) float ssh[16 * 16];
    for (int n0 = s; n0 < e; n0 += 16) {
        int cnt = min(16, e - n0);
        if (tid < cnt * 16) ssh[tid] = d_S[(size_t)n0 * KCL + tid];
        __syncthreads();
        for (int a = 0; a < cnt; a++) {
            float hgv = h[(size_t)(n0 + a) * HID + tid];
            const float4* sp = (const float4*)&ssh[a * 16];
            float4 s0 = sp[0], s1 = sp[1], s2 = sp[2], s3 = sp[3];
            acc[0]  += s0.x * hgv; acc[1]  += s0.y * hgv;
            acc[2]  += s0.z * hgv; acc[3]  += s0.w * hgv;
            acc[4]  += s1.x * hgv; acc[5]  += s1.y * hgv;
            acc[6]  += s1.z * hgv; acc[7]  += s1.w * hgv;
            acc[8]  += s2.x * hgv; acc[9]  += s2.y * hgv;
            acc[10] += s2.z * hgv; acc[11] += s2.w * hgv;
            acc[12] += s3.x * hgv; acc[13] += s3.y * hgv;
            acc[14] += s3.z * hgv; acc[15] += s3.w * hgv;
        }
        __syncthreads();
    }
    #pragma unroll
    for (int k = 0; k < 16; k++)
        d_cluster[((size_t)b * 16 + k) * HID + tid] = acc[k];
}

// ---------------- K5: attention readout + folded proj + LN ---------------
__global__ __launch_bounds__(256) void k_readout(
    const float* __restrict__ gamma, const float* __restrict__ beta,
    float* __restrict__ out) {
    int b = blockIdx.x, tid = threadIdx.x, lane = tid & 31, p = tid >> 5;
    __shared__ float cl[16][HID];
    __shared__ float qm[HID][9];
    __shared__ float msh[PH][HID];
    __shared__ float wsh[PH][16];
    __shared__ float red[HID];
    __shared__ float bqs[PH];
    #pragma unroll
    for (int k = 0; k < 16; k++)
        cl[k][tid] = d_cluster[((size_t)b * 16 + k) * HID + tid];
    for (int idx = tid; idx < HID * PH; idx += 256)
        qm[idx >> 3][idx & 7] = d_Qm[idx];
    if (tid < PH) bqs[tid] = d_bq[tid];
    __syncthreads();

    float ml = 0.f;
    for (int k = 0; k < 16; k++) {
        float part = 0.f;
        #pragma unroll
        for (int i = 0; i < 8; i++) { int jj = lane + 32 * i; part += cl[k][jj] * qm[jj][p]; }
        #pragma unroll
        for (int off = 16; off; off >>= 1)
            part += __shfl_xor_sync(0xffffffffu, part, off);
        if (lane == k) ml = part;
    }
    const float scale = 0.17677669529663687f;
    if (lane < 16) {
        float lgv = (ml + bqs[p]) * scale;
        float mx = lgv;
        #pragma unroll
        for (int off = 8; off; off >>= 1)
            mx = fmaxf(mx, __shfl_xor_sync(0xffffu, mx, off, 16));
        float e = expf(lgv - mx), su = e;
        #pragma unroll
        for (int off = 8; off; off >>= 1)
            su += __shfl_xor_sync(0xffffu, su, off, 16);
        wsh[p][lane] = e / su;
    }
    __syncthreads();

    #pragma unroll
    for (int pp = 0; pp < PH; pp++) {
        float a = 0.f;
        #pragma unroll
        for (int k = 0; k < 16; k++) a += wsh[pp][k] * cl[k][tid];
        msh[pp][tid] = a;
    }
    __syncthreads();

    float o = d_bv[tid];
    #pragma unroll 8
    for (int i = 0; i < HID; i++)
        o += msh[p][i] * d_Wcv[(size_t)i * HID + tid];

    red[tid] = o; __syncthreads();
    for (int s = 128; s; s >>= 1) { if (tid < s) red[tid] += red[tid + s]; __syncthreads(); }
    float mu = red[0] * (1.f / HID);
    __syncthreads();
    float dv = o - mu;
    red[tid] = dv * dv; __syncthreads();
    for (int s = 128; s; s >>= 1) { if (tid < s) red[tid] += red[tid + s]; __syncthreads(); }
    float var = red[0] * (1.f / HID);
    out[(size_t)b * HID + tid] = dv * rsqrtf(var + 1e-5f) * gamma[tid] + beta[tid];
}

// ---------------- launch --------------------------------------------------
extern "C" void kernel_launch(void* const* d_in, const int* in_sizes, int n_in,
                              void* d_out, int out_size) {
    const float* h_atom = (const float*)d_in[0];
    const float* c_atom = (const float*)d_in[1];
    const int*   batch  = (const int*)  d_in[2];
    const float* W1 = (const float*)d_in[3];
    const float* b1 = (const float*)d_in[4];
    const float* W2 = (const float*)d_in[5];
    const float* b2 = (const float*)d_in[6];
    const float* A1 = (const float*)d_in[7];
    const float* ab1 = (const float*)d_in[8];
    const float* A2 = (const float*)d_in[9];
    const float* ab2 = (const float*)d_in[10];
    const float* Wc = (const float*)d_in[11];
    const float* bc = (const float*)d_in[12];
    const float* q  = (const float*)d_in[13];
    const float* Wk = (const float*)d_in[14];
    const float* Wv = (const float*)d_in[15];
    const float* gamma = (const float*)d_in[16];
    const float* beta  = (const float*)d_in[17];
    float* out = (float*)d_out;

    int N = in_sizes[0] / HID; if (N > NMAX) N = NMAX;
    int B = out_size / HID;    if (B > BMAX) B = BMAX;

    cudaFuncSetAttribute(k_fused, cudaFuncAttributeMaxDynamicSharedMemorySize, SMEMSZ);

    int gtiles = (N + 63) / 64;
    // observed ncu offset: my index 3 == profiled stream index 5
    k_seg<<<(N + 255) / 256, 256>>>(batch, N, B);          // 0
    k_cvtw1<<<384, 256>>>(W1);                             // 1
    k_cvta1<<<256, 256>>>(A1);                             // 2
    k_fused<<<gtiles, 256, SMEMSZ>>>(h_atom, c_atom, b1, W2, b2, ab1, A2, ab2, N);  // 3
    k_u2<<<256, 256>>>(Wk, q);                             // 4
    k_wcv<<<HID + 1, 256>>>(Wc, Wv, bc);                   // 5
    k_qm<<<HID + 1, 256>>>(Wc, bc);                        // 6
    k_pool<<<B, 256>>>(h_atom);                            // 7
    k_readout<<<B, 256>>>(gamma, beta, out);               // 8
}

// round 15
// speedup vs baseline: 1.1301x; 1.1301x over previous
#include <cuda_runtime.h>
#include <cuda_fp16.h>
#include <math.h>
#include <stdint.h>

#define HID 256
#define CND 128
#define KCL 16
#define PH  8
#define NMAX 262144
#define BMAX 2048

// ---------------- scratch (static device allocations) --------------------
__device__ float d_cluster[(size_t)BMAX * KCL * HID];   // accumulated (zeroed each run)
__device__ float d_u  [HID * PH];
__device__ float d_Qm [HID * PH];
__device__ float d_bq [PH];
__device__ float d_Wcv[HID * HID];
__device__ float d_bv [HID];
__device__ __half d_w1t[256 * 384];
__device__ __half d_a1t[256 * 256];

__device__ __forceinline__ float geluf(float x) {
    return 0.5f * x * (1.0f + erff(x * 0.7071067811865475f));
}
__device__ __forceinline__ uint32_t smem_u32(const void* p) {
    uint32_t a;
    asm("{ .reg .u64 t; cvta.to.shared.u64 t, %1; cvt.u32.u64 %0, t; }"
        : "=r"(a) : "l"(p));
    return a;
}

#define SW128(o) ((o) ^ (((o) >> 3) & 0x70))

#define LDSM_X4(r, addr) \
    asm volatile("ldmatrix.sync.aligned.m8n8.x4.shared.b16 {%0,%1,%2,%3}, [%4];" \
        : "=r"((r)[0]), "=r"((r)[1]), "=r"((r)[2]), "=r"((r)[3]) : "r"(addr))
#define MMA16816F(c, a, b) \
    asm volatile("mma.sync.aligned.m16n8k16.row.col.f32.f16.f16.f32 " \
        "{%0,%1,%2,%3}, {%4,%5,%6,%7}, {%8,%9}, {%0,%1,%2,%3};" \
        : "+f"((c)[0]), "+f"((c)[1]), "+f"((c)[2]), "+f"((c)[3]) \
        : "r"((a)[0]), "r"((a)[1]), "r"((a)[2]), "r"((a)[3]), \
          "r"((b)[0]), "r"((b)[1]))
#define CP_A16(dst, src) \
    asm volatile("cp.async.cg.shared.global [%0], [%1], 16;" \
        :: "r"(dst), "l"(src) : "memory")
#define CP_A16Z(dst, src, sz) \
    asm volatile("cp.async.cg.shared.global [%0], [%1], 16, %2;" \
        :: "r"(dst), "l"(src), "r"(sz) : "memory")
#define CP_COMMIT() asm volatile("cp.async.commit_group;" ::: "memory")
#define CP_WAIT0()  asm volatile("cp.async.wait_group 0;" ::: "memory")

// smem byte layout per CTA (64-row tile; 2 CTAs/SM)
#define S_BIAS1 0        // 256 f32
#define S_W2    1024     // 256 f32
#define S_AB1   2048     // 256 f32
#define S_AB2   3072     // 16 f32
#define S_ALPHA 3200     // 64 f32
#define S_BIDS  3456     // 64 int (batch ids for pool)
#define S_RED2  3712     // 64*16 f32 = 4096 (logits -> S)
#define AST     8192     // 16KB f32 A staging (aliased as A2 table in epi2)
#define ABF     24576    // 16KB fp16 A (hi @+0, lo @+8192)
#define BB0     40960    // 32KB fp16 B buf0 | pool h-tile [BB0, BB0+64KB)
#define BB1     73728    // 32KB fp16 B buf1
#define SMEMSZ  106496

// ---------------- tiny prep kernels --------------------------------------
__global__ void k_zero(void) {
    size_t i = (size_t)blockIdx.x * 256 + threadIdx.x;   // 8192*256 float4
    ((float4*)d_cluster)[i] = make_float4(0.f, 0.f, 0.f, 0.f);
}
__global__ void k_cvtw1(const float* __restrict__ W) {
    int t = blockIdx.x, j = threadIdx.x;            // W[384][256] -> WT[256][384]
    d_w1t[(size_t)j * 384 + t] = __float2half_rn(W[(size_t)t * 256 + j]);
}
__global__ void k_cvta1(const float* __restrict__ A) {
    int t = blockIdx.x, j = threadIdx.x;
    d_a1t[(size_t)j * 256 + t] = __float2half_rn(A[(size_t)t * 256 + j]);
}

// ---------------- readout prep (parallel) --------------------------------
__global__ void k_u2(const float* __restrict__ Wk, const float* __restrict__ q) {
    __shared__ float qs[HID];
    int tid = threadIdx.x, t = blockIdx.x;
    qs[tid] = q[tid];
    __syncthreads();
    int lane = tid & 31, p = tid >> 5;
    float v = Wk[(size_t)t * HID + tid] * qs[tid];
    #pragma unroll
    for (int off = 16; off; off >>= 1)
        v += __shfl_xor_sync(0xffffffffu, v, off);
    if (lane == 0) d_u[t * PH + p] = v;
}
__global__ __launch_bounds__(256) void k_wcv(
    const float* __restrict__ Wc, const float* __restrict__ Wv,
    const float* __restrict__ bc) {
    int i = blockIdx.x, j = threadIdx.x;
    float a = 0.f;
    if (i < HID) {
        #pragma unroll 4
        for (int t = 0; t < HID; t++)
            a += Wc[(size_t)i * HID + t] * Wv[(size_t)t * HID + j];
        d_Wcv[(size_t)i * HID + j] = a;
    } else {
        #pragma unroll 4
        for (int t = 0; t < HID; t++)
            a += bc[t] * Wv[(size_t)t * HID + j];
        d_bv[j] = a;
    }
}
__global__ __launch_bounds__(256) void k_qm(
    const float* __restrict__ Wc, const float* __restrict__ bc) {
    __shared__ float wrow[HID];
    int i = blockIdx.x, tid = threadIdx.x;
    wrow[tid] = (i < HID) ? Wc[(size_t)i * HID + tid] : bc[tid];
    __syncthreads();
    int p = tid >> 5, lane = tid & 31;
    float v = 0.f;
    #pragma unroll
    for (int t = 0; t < 8; t++) {
        int idx = lane + 32 * t;
        v += wrow[idx] * d_u[idx * PH + p];
    }
    #pragma unroll
    for (int off = 16; off; off >>= 1)
        v += __shfl_xor_sync(0xffffffffu, v, off);
    if (lane == 0) { if (i < HID) d_Qm[i * PH + p] = v; else d_bq[p] = v; }
}

// ======================= fused atom kernel (fp16) =========================
template <int TWO_PASS>
__device__ __forceinline__ void mma_block(uint32_t abf, uint32_t bbase,
                                          int lane, int wm, int wn,
                                          float acc[2][8][4]) {
    #pragma unroll
    for (int ks = 0; ks < 4; ks++) {
        int kb = ks * 32;
        uint32_t ah[2][4], al[2][4];
        #pragma unroll
        for (int mt = 0; mt < 2; mt++) {
            int mb = wm * 32 + mt * 16 + (lane & 7) + ((lane & 8) ? 8 : 0);
            uint32_t ao = SW128((uint32_t)(mb * 128 + kb + ((lane & 16) ? 16 : 0)));
            LDSM_X4(ah[mt], abf + ao);
            if (TWO_PASS) LDSM_X4(al[mt], abf + 8192 + ao);
        }
        #pragma unroll
        for (int np = 0; np < 4; np++) {
            int nb = wn * 64 + (np * 2 + ((lane >> 4) & 1)) * 8 + (lane & 7);
            uint32_t bo = SW128((uint32_t)(nb * 128 + kb + ((lane & 8) ? 16 : 0)));
            uint32_t bh[4];
            LDSM_X4(bh, bbase + bo);
            MMA16816F(acc[0][2*np],   ah[0], bh);
            MMA16816F(acc[1][2*np],   ah[1], bh);
            MMA16816F(acc[0][2*np+1], ah[0], bh + 2);
            MMA16816F(acc[1][2*np+1], ah[1], bh + 2);
            if (TWO_PASS) {
                MMA16816F(acc[0][2*np],   al[0], bh);
                MMA16816F(acc[1][2*np],   al[1], bh);
                MMA16816F(acc[0][2*np+1], al[0], bh + 2);
                MMA16816F(acc[1][2*np+1], al[1], bh + 2);
            }
        }
    }
}

__global__ void __launch_bounds__(256, 2) k_fused(
    const float* __restrict__ h, const float* __restrict__ c,
    const int* __restrict__ batch,
    const float* __restrict__ b1, const float* __restrict__ W2,
    const float* __restrict__ b2, const float* __restrict__ ab1,
    const float* __restrict__ A2, const float* __restrict__ ab2, int N) {
    extern __shared__ __align__(1024) char smem[];
    uint32_t sb = smem_u32(smem);
    int tid = threadIdx.x, lane = tid & 31, wid = tid >> 5;
    int wm = wid & 1, wn = wid >> 1;     // 2 x 4 warp grid: 64 rows x 256 cols
    int r0 = blockIdx.x * 64;

    float* bias1 = (float*)(smem + S_BIAS1);
    float* w2s   = (float*)(smem + S_W2);
    float* ab1s  = (float*)(smem + S_AB1);
    float* ab2s  = (float*)(smem + S_AB2);
    float* alpha = (float*)(smem + S_ALPHA);
    int*   bids  = (int*)  (smem + S_BIDS);
    float* red2  = (float*)(smem + S_RED2);

    bias1[tid] = b1[tid];
    w2s[tid]   = W2[tid];
    ab1s[tid]  = ab1[tid];
    if (tid < 16) ab2s[tid] = ab2[tid];
    if (tid < 64) alpha[tid] = 0.f;
    for (int i = tid; i < 64 * 16; i += 256) red2[i] = 0.f;

    // per-thread load coordinates
    int a_row = tid >> 4, a_c4 = (tid & 15) * 4;
    int b_row = tid >> 3, b_u8 = (tid & 7) * 8;

    auto issueA = [&](const float* src1, int ch) {
        int kt = ch * 64;
        const float* src; int stride, cb;
        if (kt < 256) { src = src1; stride = 256; cb = kt; }
        else          { src = c;    stride = 128; cb = kt - 256; }
        #pragma unroll
        for (int i = 0; i < 4; i++) {
            int idx = tid + i * 256;
            int row = a_row + i * 16;
            int gr = r0 + row;
            const float* sp = src + (size_t)gr * stride + cb + a_c4;
            int sz = (gr < N) ? 16 : 0;
            CP_A16Z(sb + AST + idx * 16, sp, sz);
        }
    };
    auto issueB = [&](const __half* Bt, int stride, int ch, uint32_t bbuf) {
        int kt = ch * 64;
        #pragma unroll
        for (int i = 0; i < 8; i++) {
            int row = b_row + i * 32;
            uint32_t off = SW128((uint32_t)(row * 128 + b_u8 * 2));
            CP_A16(sb + bbuf + off, Bt + (size_t)row * stride + kt + b_u8);
        }
    };

    float acc[2][8][4];
    #pragma unroll
    for (int a = 0; a < 2; a++)
        #pragma unroll
        for (int b = 0; b < 8; b++)
            #pragma unroll
            for (int e = 0; e < 4; e++) acc[a][b][e] = 0.f;

    // =================== phase 1: D1 = [h|c] @ W1  (1-pass) ==============
    issueA(h, 0);
    issueB(d_w1t, 384, 0, BB0);
    CP_COMMIT();
    for (int ch = 0; ch < 6; ch++) {
        uint32_t bbuf = (ch & 1) ? BB1 : BB0;
        CP_WAIT0();
        __syncthreads();
        #pragma unroll
        for (int i = 0; i < 4; i++) {
            int idx = tid + i * 256;
            int row = a_row + i * 16;
            float4 v = *(const float4*)(smem + AST + idx * 16);
            __half h0 = __float2half_rn(v.x), h1 = __float2half_rn(v.y);
            __half h2 = __float2half_rn(v.z), h3 = __float2half_rn(v.w);
            uint32_t off = SW128((uint32_t)(row * 128 + a_c4 * 2));
            uint2 ph_ = make_uint2(
                (uint32_t)__half_as_ushort(h0) | ((uint32_t)__half_as_ushort(h1) << 16),
                (uint32_t)__half_as_ushort(h2) | ((uint32_t)__half_as_ushort(h3) << 16));
            *(uint2*)(smem + ABF + off) = ph_;
        }
        if (ch < 5) {
            issueA(h, ch + 1);
            issueB(d_w1t, 384, ch + 1, (ch & 1) ? BB0 : BB1);
        } else {
            issueA(h, 0);               // phase-2 chunk0 (alpha-independent)
            issueB(d_a1t, 256, 0, BB0);
        }
        CP_COMMIT();
        __syncthreads();
        mma_block<0>(sb + ABF, sb + bbuf, lane, wm, wn, acc);
    }
    // =================== epilogue 1: gate -> alpha =======================
    {
        float* redg = alpha;  // reuse: accumulate into alpha region then transform
        // (alpha[] was zero-initialized above)
        #pragma unroll
        for (int mt = 0; mt < 2; mt++) {
            float s0 = 0.f, s1 = 0.f;
            #pragma unroll
            for (int nt = 0; nt < 8; nt++) {
                int n = wn * 64 + nt * 8 + (lane & 3) * 2;
                float b0v = bias1[n], b1v = bias1[n + 1];
                float w0 = w2s[n], w1v = w2s[n + 1];
                s0 += geluf(acc[mt][nt][0] + b0v) * w0 + geluf(acc[mt][nt][1] + b1v) * w1v;
                s1 += geluf(acc[mt][nt][2] + b0v) * w0 + geluf(acc[mt][nt][3] + b1v) * w1v;
            }
            s0 += __shfl_xor_sync(0xffffffffu, s0, 1);
            s0 += __shfl_xor_sync(0xffffffffu, s0, 2);
            s1 += __shfl_xor_sync(0xffffffffu, s1, 1);
            s1 += __shfl_xor_sync(0xffffffffu, s1, 2);
            if ((lane & 3) == 0) {
                int r = wm * 32 + mt * 16 + (lane >> 2);
                atomicAdd(&redg[r], s0);
                atomicAdd(&redg[r + 8], s1);
            }
        }
        __syncthreads();
        if (tid < 64) alpha[tid] = 1.f / (1.f + expf(-(alpha[tid] + b2[0])));
    }
    // =================== phase 2: E = h @ A1  (2-pass) ===================
    #pragma unroll
    for (int a = 0; a < 2; a++)
        #pragma unroll
        for (int b = 0; b < 8; b++)
            #pragma unroll
            for (int e = 0; e < 4; e++) acc[a][b][e] = 0.f;

    for (int ch = 0; ch < 4; ch++) {
        uint32_t bbuf = (ch & 1) ? BB1 : BB0;
        CP_WAIT0();
        __syncthreads();
        #pragma unroll
        for (int i = 0; i < 4; i++) {
            int idx = tid + i * 256;
            int row = a_row + i * 16;
            float4 v = *(const float4*)(smem + AST + idx * 16);
            __half h0 = __float2half_rn(v.x), h1 = __float2half_rn(v.y);
            __half h2 = __float2half_rn(v.z), h3 = __float2half_rn(v.w);
            __half l0 = __float2half_rn(v.x - __half2float(h0));
            __half l1 = __float2half_rn(v.y - __half2float(h1));
            __half l2 = __float2half_rn(v.z - __half2float(h2));
            __half l3 = __float2half_rn(v.w - __half2float(h3));
            uint32_t off = SW128((uint32_t)(row * 128 + a_c4 * 2));
            uint2 ph_ = make_uint2(
                (uint32_t)__half_as_ushort(h0) | ((uint32_t)__half_as_ushort(h1) << 16),
                (uint32_t)__half_as_ushort(h2) | ((uint32_t)__half_as_ushort(h3) << 16));
            uint2 pl_ = make_uint2(
                (uint32_t)__half_as_ushort(l0) | ((uint32_t)__half_as_ushort(l1) << 16),
                (uint32_t)__half_as_ushort(l2) | ((uint32_t)__half_as_ushort(l3) << 16));
            *(uint2*)(smem + ABF + off) = ph_;
            *(uint2*)(smem + ABF + 8192 + off) = pl_;
        }
        if (ch < 3) {
            issueA(h, ch + 1);
            issueB(d_a1t, 256, ch + 1, (ch & 1) ? BB0 : BB1);
        }
        CP_COMMIT();
        __syncthreads();
        mma_block<1>(sb + ABF, sb + bbuf, lane, wm, wn, acc);
    }
    __syncthreads();   // all warps done reading BB0/BB1
    // prefetch full h tile [64 x 256] f32 into BB0..BB0+64KB (overlaps epi2)
    #pragma unroll
    for (int i = 0; i < 16; i++) {
        int idx = tid + i * 256;                 // 4096 float4 units
        int row = idx >> 6, c4 = (idx & 63) * 4;
        int gr = r0 + row;
        const float* sp = h + (size_t)gr * 256 + c4;
        int sz = (gr < N) ? 16 : 0;
        CP_A16Z(sb + BB0 + idx * 16, sp, sz);
    }
    CP_COMMIT();
    // load A2 table into AST (thread-private slots, then sync for cross-reads)
    {
        float* a2s = (float*)(smem + AST);
        for (int i = tid; i < 256 * 16; i += 256) a2s[i] = A2[i];
    }
    // batch ids for pool
    if (tid < 64) {
        int gr = r0 + tid;
        bids[tid] = (gr < N) ? batch[gr] : -1;
    }
    __syncthreads();
    // ============ epilogue 2: alpha-scale + @A2 -> logits in red2 ========
    {
        const float* a2s = (const float*)(smem + AST);
        #pragma unroll
        for (int mt = 0; mt < 2; mt++) {
            float l0[16], l1[16];
            #pragma unroll
            for (int k = 0; k < 16; k++) { l0[k] = 0.f; l1[k] = 0.f; }
            float ar0 = alpha[wm * 32 + mt * 16 + (lane >> 2)];
            float ar1 = alpha[wm * 32 + mt * 16 + (lane >> 2) + 8];
            #pragma unroll
            for (int nt = 0; nt < 8; nt++) {
                int n = wn * 64 + nt * 8 + (lane & 3) * 2;
                #pragma unroll
                for (int e = 0; e < 4; e++) {
                    int col = n + (e & 1);
                    float av = (e < 2) ? ar0 : ar1;
                    float v = geluf(av * acc[mt][nt][e] + ab1s[col]);
                    const float* ar = &a2s[col * 16];
                    float* dst = (e < 2) ? l0 : l1;
                    #pragma unroll
                    for (int k = 0; k < 16; k++) dst[k] += v * ar[k];
                }
            }
            #pragma unroll
            for (int k = 0; k < 16; k++) {
                l0[k] += __shfl_xor_sync(0xffffffffu, l0[k], 1);
                l0[k] += __shfl_xor_sync(0xffffffffu, l0[k], 2);
                l1[k] += __shfl_xor_sync(0xffffffffu, l1[k], 1);
                l1[k] += __shfl_xor_sync(0xffffffffu, l1[k], 2);
            }
            if ((lane & 3) == 0) {
                int r = wm * 32 + mt * 16 + (lane >> 2);
                #pragma unroll
                for (int k = 0; k < 16; k++) {
                    atomicAdd(&red2[r * 16 + k], l0[k]);
                    atomicAdd(&red2[(r + 8) * 16 + k], l1[k]);
                }
            }
        }
    }
    __syncthreads();
    // softmax * alpha -> S, stored back into red2 (row-owner threads)
    if (tid < 64) {
        int gr = r0 + tid;
        if (gr < N) {
            float l[16], mx = -1e30f;
            #pragma unroll
            for (int k = 0; k < 16; k++) {
                l[k] = red2[tid * 16 + k] + ab2s[k];
                mx = fmaxf(mx, l[k]);
            }
            float s = 0.f;
            #pragma unroll
            for (int k = 0; k < 16; k++) { l[k] = expf(l[k] - mx); s += l[k]; }
            float inv = alpha[tid] / s;
            #pragma unroll
            for (int k = 0; k < 16; k++) red2[tid * 16 + k] = l[k] * inv;
        } else {
            #pragma unroll
            for (int k = 0; k < 16; k++) red2[tid * 16 + k] = 0.f;
        }
    }
    CP_WAIT0();          // h tile landed
    __syncthreads();
    // ============ fused segment pool: d_cluster[b,k,j] += S[n,k]*h[n,j] ==
    {
        const float* hsm = (const float*)(smem + BB0);
        float pacc[16];
        #pragma unroll
        for (int k = 0; k < 16; k++) pacc[k] = 0.f;
        int cur = bids[0];
        for (int n = 0; n < 64; n++) {
            int bn = bids[n];
            if (bn != cur) {
                if (cur >= 0) {
                    #pragma unroll
                    for (int k = 0; k < 16; k++)
                        atomicAdd(&d_cluster[((size_t)cur * 16 + k) * HID + tid], pacc[k]);
                }
                #pragma unroll
                for (int k = 0; k < 16; k++) pacc[k] = 0.f;
                cur = bn;
            }
            float hv = hsm[n * HID + tid];
            const float* sr = &red2[n * 16];
            #pragma unroll
            for (int k = 0; k < 16; k++) pacc[k] += sr[k] * hv;
        }
        if (cur >= 0) {
            #pragma unroll
            for (int k = 0; k < 16; k++)
                atomicAdd(&d_cluster[((size_t)cur * 16 + k) * HID + tid], pacc[k]);
        }
    }
}

// ---------------- K5: attention readout + folded proj + LN ---------------
__global__ __launch_bounds__(256) void k_readout(
    const float* __restrict__ gamma, const float* __restrict__ beta,
    float* __restrict__ out) {
    int b = blockIdx.x, tid = threadIdx.x, lane = tid & 31, p = tid >> 5;
    __shared__ float cl[16][HID];
    __shared__ float qm[HID][9];
    __shared__ float msh[PH][HID];
    __shared__ float wsh[PH][16];
    __shared__ float red[HID];
    __shared__ float bqs[PH];
    #pragma unroll
    for (int k = 0; k < 16; k++)
        cl[k][tid] = d_cluster[((size_t)b * 16 + k) * HID + tid];
    for (int idx = tid; idx < HID * PH; idx += 256)
        qm[idx >> 3][idx & 7] = d_Qm[idx];
    if (tid < PH) bqs[tid] = d_bq[tid];
    __syncthreads();

    float ml = 0.f;
    for (int k = 0; k < 16; k++) {
        float part = 0.f;
        #pragma unroll
        for (int i = 0; i < 8; i++) { int jj = lane + 32 * i; part += cl[k][jj] * qm[jj][p]; }
        #pragma unroll
        for (int off = 16; off; off >>= 1)
            part += __shfl_xor_sync(0xffffffffu, part, off);
        if (lane == k) ml = part;
    }
    const float scale = 0.17677669529663687f;
    if (lane < 16) {
        float lgv = (ml + bqs[p]) * scale;
        float mx = lgv;
        #pragma unroll
        for (int off = 8; off; off >>= 1)
            mx = fmaxf(mx, __shfl_xor_sync(0xffffu, mx, off, 16));
        float e = expf(lgv - mx), su = e;
        #pragma unroll
        for (int off = 8; off; off >>= 1)
            su += __shfl_xor_sync(0xffffu, su, off, 16);
        wsh[p][lane] = e / su;
    }
    __syncthreads();

    #pragma unroll
    for (int pp = 0; pp < PH; pp++) {
        float a = 0.f;
        #pragma unroll
        for (int k = 0; k < 16; k++) a += wsh[pp][k] * cl[k][tid];
        msh[pp][tid] = a;
    }
    __syncthreads();

    float o = d_bv[tid];
    #pragma unroll 8
    for (int i = 0; i < HID; i++)
        o += msh[p][i] * d_Wcv[(size_t)i * HID + tid];

    red[tid] = o; __syncthreads();
    for (int s = 128; s; s >>= 1) { if (tid < s) red[tid] += red[tid + s]; __syncthreads(); }
    float mu = red[0] * (1.f / HID);
    __syncthreads();
    float dv = o - mu;
    red[tid] = dv * dv; __syncthreads();
    for (int s = 128; s; s >>= 1) { if (tid < s) red[tid] += red[tid + s]; __syncthreads(); }
    float var = red[0] * (1.f / HID);
    out[(size_t)b * HID + tid] = dv * rsqrtf(var + 1e-5f) * gamma[tid] + beta[tid];
}

// ---------------- launch --------------------------------------------------
extern "C" void kernel_launch(void* const* d_in, const int* in_sizes, int n_in,
                              void* d_out, int out_size) {
    const float* h_atom = (const float*)d_in[0];
    const float* c_atom = (const float*)d_in[1];
    const int*   batch  = (const int*)  d_in[2];
    const float* W1 = (const float*)d_in[3];
    const float* b1 = (const float*)d_in[4];
    const float* W2 = (const float*)d_in[5];
    const float* b2 = (const float*)d_in[6];
    const float* A1 = (const float*)d_in[7];
    const float* ab1 = (const float*)d_in[8];
    const float* A2 = (const float*)d_in[9];
    const float* ab2 = (const float*)d_in[10];
    const float* Wc = (const float*)d_in[11];
    const float* bc = (const float*)d_in[12];
    const float* q  = (const float*)d_in[13];
    const float* Wk = (const float*)d_in[14];
    const float* Wv = (const float*)d_in[15];
    const float* gamma = (const float*)d_in[16];
    const float* beta  = (const float*)d_in[17];
    float* out = (float*)d_out;

    int N = in_sizes[0] / HID; if (N > NMAX) N = NMAX;
    int B = out_size / HID;    if (B > BMAX) B = BMAX;

    cudaFuncSetAttribute(k_fused, cudaFuncAttributeMaxDynamicSharedMemorySize, SMEMSZ);

    int gtiles = (N + 63) / 64;
    // observed ncu offset: my index 3 == profiled stream index 5
    k_zero<<<8192, 256>>>();                               // 0
    k_cvtw1<<<384, 256>>>(W1);                             // 1
    k_cvta1<<<256, 256>>>(A1);                             // 2
    k_fused<<<gtiles, 256, SMEMSZ>>>(h_atom, c_atom, batch,
                                     b1, W2, b2, ab1, A2, ab2, N);  // 3
    k_u2<<<256, 256>>>(Wk, q);                             // 4
    k_wcv<<<HID + 1, 256>>>(Wc, Wv, bc);                   // 5
    k_qm<<<HID + 1, 256>>>(Wc, bc);                        // 6
    k_readout<<<B, 256>>>(gamma, beta, out);               // 7
}

// round 16
// speedup vs baseline: 1.1406x; 1.0093x over previous
#include <cuda_runtime.h>
#include <cuda_fp16.h>
#include <math.h>
#include <stdint.h>

#define HID 256
#define CND 128
#define KCL 16
#define PH  8
#define NMAX 262144
#define BMAX 2048

// ---------------- scratch (static device allocations) --------------------
__device__ float d_cluster[(size_t)BMAX * KCL * HID];   // accumulated (zeroed each run)
__device__ float d_u  [HID * PH];
__device__ float d_Qm [HID * PH];
__device__ float d_bq [PH];
__device__ float d_Wcv[HID * HID];
__device__ float d_bv [HID];
__device__ __half d_w1t[256 * 384];
__device__ __half d_a1t[256 * 256];

__device__ __forceinline__ float geluf(float x) {
    return 0.5f * x * (1.0f + erff(x * 0.7071067811865475f));
}
__device__ __forceinline__ uint32_t smem_u32(const void* p) {
    uint32_t a;
    asm("{ .reg .u64 t; cvta.to.shared.u64 t, %1; cvt.u32.u64 %0, t; }"
        : "=r"(a) : "l"(p));
    return a;
}

#define SW128(o) ((o) ^ (((o) >> 3) & 0x70))

#define LDSM_X4(r, addr) \
    asm volatile("ldmatrix.sync.aligned.m8n8.x4.shared.b16 {%0,%1,%2,%3}, [%4];" \
        : "=r"((r)[0]), "=r"((r)[1]), "=r"((r)[2]), "=r"((r)[3]) : "r"(addr))
#define MMA16816F(c, a, b) \
    asm volatile("mma.sync.aligned.m16n8k16.row.col.f32.f16.f16.f32 " \
        "{%0,%1,%2,%3}, {%4,%5,%6,%7}, {%8,%9}, {%0,%1,%2,%3};" \
        : "+f"((c)[0]), "+f"((c)[1]), "+f"((c)[2]), "+f"((c)[3]) \
        : "r"((a)[0]), "r"((a)[1]), "r"((a)[2]), "r"((a)[3]), \
          "r"((b)[0]), "r"((b)[1]))
#define CP_A16(dst, src) \
    asm volatile("cp.async.cg.shared.global [%0], [%1], 16;" \
        :: "r"(dst), "l"(src) : "memory")
#define CP_A16Z(dst, src, sz) \
    asm volatile("cp.async.cg.shared.global [%0], [%1], 16, %2;" \
        :: "r"(dst), "l"(src), "r"(sz) : "memory")
#define CP_COMMIT() asm volatile("cp.async.commit_group;" ::: "memory")
#define CP_WAIT0()  asm volatile("cp.async.wait_group 0;" ::: "memory")

// smem byte layout per CTA (64-row tile; 2 CTAs/SM)
#define S_BIAS1 0        // 256 f32
#define S_W2    1024     // 256 f32
#define S_AB1   2048     // 256 f32
#define S_AB2   3072     // 16 f32
#define S_ALPHA 3200     // 64 f32
#define S_BIDS  3456     // 64 int (batch ids for pool)
#define S_RED2  3712     // 64*16 f32 = 4096 (logits -> S)
#define AST     8192     // 16KB f32 A staging (aliased as A2 table in epi2)
#define ABF     24576    // 16KB fp16 A (hi only used now)
#define BB0     40960    // 32KB fp16 B buf0 | pool h-tile [BB0, BB0+64KB)
#define BB1     73728    // 32KB fp16 B buf1
#define SMEMSZ  106496

// ---------------- tiny prep kernels --------------------------------------
__global__ void k_zero(void) {
    size_t i = (size_t)blockIdx.x * 256 + threadIdx.x;   // 8192*256 float4
    ((float4*)d_cluster)[i] = make_float4(0.f, 0.f, 0.f, 0.f);
}
__global__ void k_cvtw1(const float* __restrict__ W) {
    int t = blockIdx.x, j = threadIdx.x;            // W[384][256] -> WT[256][384]
    d_w1t[(size_t)j * 384 + t] = __float2half_rn(W[(size_t)t * 256 + j]);
}
__global__ void k_cvta1(const float* __restrict__ A) {
    int t = blockIdx.x, j = threadIdx.x;
    d_a1t[(size_t)j * 256 + t] = __float2half_rn(A[(size_t)t * 256 + j]);
}

// ---------------- readout prep (parallel) --------------------------------
__global__ void k_u2(const float* __restrict__ Wk, const float* __restrict__ q) {
    __shared__ float qs[HID];
    int tid = threadIdx.x, t = blockIdx.x;
    qs[tid] = q[tid];
    __syncthreads();
    int lane = tid & 31, p = tid >> 5;
    float v = Wk[(size_t)t * HID + tid] * qs[tid];
    #pragma unroll
    for (int off = 16; off; off >>= 1)
        v += __shfl_xor_sync(0xffffffffu, v, off);
    if (lane == 0) d_u[t * PH + p] = v;
}
__global__ __launch_bounds__(256) void k_wcv(
    const float* __restrict__ Wc, const float* __restrict__ Wv,
    const float* __restrict__ bc) {
    int i = blockIdx.x, j = threadIdx.x;
    float a = 0.f;
    if (i < HID) {
        #pragma unroll 4
        for (int t = 0; t < HID; t++)
            a += Wc[(size_t)i * HID + t] * Wv[(size_t)t * HID + j];
        d_Wcv[(size_t)i * HID + j] = a;
    } else {
        #pragma unroll 4
        for (int t = 0; t < HID; t++)
            a += bc[t] * Wv[(size_t)t * HID + j];
        d_bv[j] = a;
    }
}
__global__ __launch_bounds__(256) void k_qm(
    const float* __restrict__ Wc, const float* __restrict__ bc) {
    __shared__ float wrow[HID];
    int i = blockIdx.x, tid = threadIdx.x;
    wrow[tid] = (i < HID) ? Wc[(size_t)i * HID + tid] : bc[tid];
    __syncthreads();
    int p = tid >> 5, lane = tid & 31;
    float v = 0.f;
    #pragma unroll
    for (int t = 0; t < 8; t++) {
        int idx = lane + 32 * t;
        v += wrow[idx] * d_u[idx * PH + p];
    }
    #pragma unroll
    for (int off = 16; off; off >>= 1)
        v += __shfl_xor_sync(0xffffffffu, v, off);
    if (lane == 0) { if (i < HID) d_Qm[i * PH + p] = v; else d_bq[p] = v; }
}

// ======================= fused atom kernel (fp16 1-pass) ==================
__device__ __forceinline__ void mma_block(uint32_t abf, uint32_t bbase,
                                          int lane, int wm, int wn,
                                          float acc[2][8][4]) {
    #pragma unroll
    for (int ks = 0; ks < 4; ks++) {
        int kb = ks * 32;
        uint32_t ah[2][4];
        #pragma unroll
        for (int mt = 0; mt < 2; mt++) {
            int mb = wm * 32 + mt * 16 + (lane & 7) + ((lane & 8) ? 8 : 0);
            uint32_t ao = SW128((uint32_t)(mb * 128 + kb + ((lane & 16) ? 16 : 0)));
            LDSM_X4(ah[mt], abf + ao);
        }
        #pragma unroll
        for (int np = 0; np < 4; np++) {
            int nb = wn * 64 + (np * 2 + ((lane >> 4) & 1)) * 8 + (lane & 7);
            uint32_t bo = SW128((uint32_t)(nb * 128 + kb + ((lane & 8) ? 16 : 0)));
            uint32_t bh[4];
            LDSM_X4(bh, bbase + bo);
            MMA16816F(acc[0][2*np],   ah[0], bh);
            MMA16816F(acc[1][2*np],   ah[1], bh);
            MMA16816F(acc[0][2*np+1], ah[0], bh + 2);
            MMA16816F(acc[1][2*np+1], ah[1], bh + 2);
        }
    }
}

__global__ void __launch_bounds__(256, 2) k_fused(
    const float* __restrict__ h, const float* __restrict__ c,
    const int* __restrict__ batch,
    const float* __restrict__ b1, const float* __restrict__ W2,
    const float* __restrict__ b2, const float* __restrict__ ab1,
    const float* __restrict__ A2, const float* __restrict__ ab2, int N) {
    extern __shared__ __align__(1024) char smem[];
    uint32_t sb = smem_u32(smem);
    int tid = threadIdx.x, lane = tid & 31, wid = tid >> 5;
    int wm = wid & 1, wn = wid >> 1;     // 2 x 4 warp grid: 64 rows x 256 cols
    int r0 = blockIdx.x * 64;

    float* bias1 = (float*)(smem + S_BIAS1);
    float* w2s   = (float*)(smem + S_W2);
    float* ab1s  = (float*)(smem + S_AB1);
    float* ab2s  = (float*)(smem + S_AB2);
    float* alpha = (float*)(smem + S_ALPHA);
    int*   bids  = (int*)  (smem + S_BIDS);
    float* red2  = (float*)(smem + S_RED2);

    bias1[tid] = b1[tid];
    w2s[tid]   = W2[tid];
    ab1s[tid]  = ab1[tid];
    if (tid < 16) ab2s[tid] = ab2[tid];
    if (tid < 64) alpha[tid] = 0.f;
    for (int i = tid; i < 64 * 16; i += 256) red2[i] = 0.f;

    // per-thread load coordinates
    int a_row = tid >> 4, a_c4 = (tid & 15) * 4;
    int b_row = tid >> 3, b_u8 = (tid & 7) * 8;

    auto issueA = [&](const float* src1, int ch) {
        int kt = ch * 64;
        const float* src; int stride, cb;
        if (kt < 256) { src = src1; stride = 256; cb = kt; }
        else          { src = c;    stride = 128; cb = kt - 256; }
        #pragma unroll
        for (int i = 0; i < 4; i++) {
            int idx = tid + i * 256;
            int row = a_row + i * 16;
            int gr = r0 + row;
            const float* sp = src + (size_t)gr * stride + cb + a_c4;
            int sz = (gr < N) ? 16 : 0;
            CP_A16Z(sb + AST + idx * 16, sp, sz);
        }
    };
    auto issueB = [&](const __half* Bt, int stride, int ch, uint32_t bbuf) {
        int kt = ch * 64;
        #pragma unroll
        for (int i = 0; i < 8; i++) {
            int row = b_row + i * 32;
            uint32_t off = SW128((uint32_t)(row * 128 + b_u8 * 2));
            CP_A16(sb + bbuf + off, Bt + (size_t)row * stride + kt + b_u8);
        }
    };
    auto splitA = [&]() {                // hi only (1-pass both phases)
        #pragma unroll
        for (int i = 0; i < 4; i++) {
            int idx = tid + i * 256;
            int row = a_row + i * 16;
            float4 v = *(const float4*)(smem + AST + idx * 16);
            __half h0 = __float2half_rn(v.x), h1 = __float2half_rn(v.y);
            __half h2 = __float2half_rn(v.z), h3 = __float2half_rn(v.w);
            uint32_t off = SW128((uint32_t)(row * 128 + a_c4 * 2));
            uint2 ph_ = make_uint2(
                (uint32_t)__half_as_ushort(h0) | ((uint32_t)__half_as_ushort(h1) << 16),
                (uint32_t)__half_as_ushort(h2) | ((uint32_t)__half_as_ushort(h3) << 16));
            *(uint2*)(smem + ABF + off) = ph_;
        }
    };

    float acc[2][8][4];
    #pragma unroll
    for (int a = 0; a < 2; a++)
        #pragma unroll
        for (int b = 0; b < 8; b++)
            #pragma unroll
            for (int e = 0; e < 4; e++) acc[a][b][e] = 0.f;

    // =================== phase 1: D1 = [h|c] @ W1 ========================
    issueA(h, 0);
    issueB(d_w1t, 384, 0, BB0);
    CP_COMMIT();
    for (int ch = 0; ch < 6; ch++) {
        uint32_t bbuf = (ch & 1) ? BB1 : BB0;
        CP_WAIT0();
        __syncthreads();
        splitA();
        if (ch < 5) {
            issueA(h, ch + 1);
            issueB(d_w1t, 384, ch + 1, (ch & 1) ? BB0 : BB1);
        } else {
            issueA(h, 0);               // phase-2 chunk0 (alpha-independent)
            issueB(d_a1t, 256, 0, BB0);
        }
        CP_COMMIT();
        __syncthreads();
        mma_block(sb + ABF, sb + bbuf, lane, wm, wn, acc);
    }
    // =================== epilogue 1: gate -> alpha =======================
    {
        #pragma unroll
        for (int mt = 0; mt < 2; mt++) {
            float s0 = 0.f, s1 = 0.f;
            #pragma unroll
            for (int nt = 0; nt < 8; nt++) {
                int n = wn * 64 + nt * 8 + (lane & 3) * 2;
                float b0v = bias1[n], b1v = bias1[n + 1];
                float w0 = w2s[n], w1v = w2s[n + 1];
                s0 += geluf(acc[mt][nt][0] + b0v) * w0 + geluf(acc[mt][nt][1] + b1v) * w1v;
                s1 += geluf(acc[mt][nt][2] + b0v) * w0 + geluf(acc[mt][nt][3] + b1v) * w1v;
            }
            s0 += __shfl_xor_sync(0xffffffffu, s0, 1);
            s0 += __shfl_xor_sync(0xffffffffu, s0, 2);
            s1 += __shfl_xor_sync(0xffffffffu, s1, 1);
            s1 += __shfl_xor_sync(0xffffffffu, s1, 2);
            if ((lane & 3) == 0) {
                int r = wm * 32 + mt * 16 + (lane >> 2);
                atomicAdd(&alpha[r], s0);
                atomicAdd(&alpha[r + 8], s1);
            }
        }
        __syncthreads();
        if (tid < 64) alpha[tid] = 1.f / (1.f + expf(-(alpha[tid] + b2[0])));
    }
    // =================== phase 2: E = h @ A1  (1-pass) ===================
    #pragma unroll
    for (int a = 0; a < 2; a++)
        #pragma unroll
        for (int b = 0; b < 8; b++)
            #pragma unroll
            for (int e = 0; e < 4; e++) acc[a][b][e] = 0.f;

    for (int ch = 0; ch < 4; ch++) {
        uint32_t bbuf = (ch & 1) ? BB1 : BB0;
        CP_WAIT0();
        __syncthreads();
        splitA();
        if (ch < 3) {
            issueA(h, ch + 1);
            issueB(d_a1t, 256, ch + 1, (ch & 1) ? BB0 : BB1);
        }
        CP_COMMIT();
        __syncthreads();
        mma_block(sb + ABF, sb + bbuf, lane, wm, wn, acc);
    }
    __syncthreads();   // all warps done reading BB0/BB1
    // prefetch full h tile [64 x 256] f32 into BB0..BB0+64KB (overlaps epi2)
    #pragma unroll
    for (int i = 0; i < 16; i++) {
        int idx = tid + i * 256;                 // 4096 float4 units
        int row = idx >> 6, c4 = (idx & 63) * 4;
        int gr = r0 + row;
        const float* sp = h + (size_t)gr * 256 + c4;
        int sz = (gr < N) ? 16 : 0;
        CP_A16Z(sb + BB0 + idx * 16, sp, sz);
    }
    CP_COMMIT();
    {
        float* a2s = (float*)(smem + AST);
        for (int i = tid; i < 256 * 16; i += 256) a2s[i] = A2[i];
    }
    if (tid < 64) {
        int gr = r0 + tid;
        bids[tid] = (gr < N) ? batch[gr] : -1;
    }
    __syncthreads();
    // ============ epilogue 2: alpha-scale + @A2 -> logits in red2 ========
    {
        const float* a2s = (const float*)(smem + AST);
        #pragma unroll
        for (int mt = 0; mt < 2; mt++) {
            float l0[16], l1[16];
            #pragma unroll
            for (int k = 0; k < 16; k++) { l0[k] = 0.f; l1[k] = 0.f; }
            float ar0 = alpha[wm * 32 + mt * 16 + (lane >> 2)];
            float ar1 = alpha[wm * 32 + mt * 16 + (lane >> 2) + 8];
            #pragma unroll
            for (int nt = 0; nt < 8; nt++) {
                int n = wn * 64 + nt * 8 + (lane & 3) * 2;
                #pragma unroll
                for (int e = 0; e < 4; e++) {
                    int col = n + (e & 1);
                    float av = (e < 2) ? ar0 : ar1;
                    float v = geluf(av * acc[mt][nt][e] + ab1s[col]);
                    const float* ar = &a2s[col * 16];
                    float* dst = (e < 2) ? l0 : l1;
                    #pragma unroll
                    for (int k = 0; k < 16; k++) dst[k] += v * ar[k];
                }
            }
            #pragma unroll
            for (int k = 0; k < 16; k++) {
                l0[k] += __shfl_xor_sync(0xffffffffu, l0[k], 1);
                l0[k] += __shfl_xor_sync(0xffffffffu, l0[k], 2);
                l1[k] += __shfl_xor_sync(0xffffffffu, l1[k], 1);
                l1[k] += __shfl_xor_sync(0xffffffffu, l1[k], 2);
            }
            if ((lane & 3) == 0) {
                int r = wm * 32 + mt * 16 + (lane >> 2);
                #pragma unroll
                for (int k = 0; k < 16; k++) {
                    atomicAdd(&red2[r * 16 + k], l0[k]);
                    atomicAdd(&red2[(r + 8) * 16 + k], l1[k]);
                }
            }
        }
    }
    __syncthreads();
    // softmax * alpha -> S (in red2)
    if (tid < 64) {
        int gr = r0 + tid;
        if (gr < N) {
            float l[16], mx = -1e30f;
            #pragma unroll
            for (int k = 0; k < 16; k++) {
                l[k] = red2[tid * 16 + k] + ab2s[k];
                mx = fmaxf(mx, l[k]);
            }
            float s = 0.f;
            #pragma unroll
            for (int k = 0; k < 16; k++) { l[k] = expf(l[k] - mx); s += l[k]; }
            float inv = alpha[tid] / s;
            #pragma unroll
            for (int k = 0; k < 16; k++) red2[tid * 16 + k] = l[k] * inv;
        } else {
            #pragma unroll
            for (int k = 0; k < 16; k++) red2[tid * 16 + k] = 0.f;
        }
    }
    CP_WAIT0();          // h tile landed
    __syncthreads();
    // ============ fused segment pool: d_cluster[b,k,j] += S[n,k]*h[n,j] ==
    {
        const float* hsm = (const float*)(smem + BB0);
        float pacc[16];
        #pragma unroll
        for (int k = 0; k < 16; k++) pacc[k] = 0.f;
        int cur = bids[0];
        for (int n = 0; n < 64; n++) {
            int bn = bids[n];
            if (bn != cur) {
                if (cur >= 0) {
                    #pragma unroll
                    for (int k = 0; k < 16; k++)
                        atomicAdd(&d_cluster[((size_t)cur * 16 + k) * HID + tid], pacc[k]);
                }
                #pragma unroll
                for (int k = 0; k < 16; k++) pacc[k] = 0.f;
                cur = bn;
            }
            float hv = hsm[n * HID + tid];
            const float4* sr = (const float4*)&red2[n * 16];
            float4 s0 = sr[0], s1 = sr[1], s2 = sr[2], s3 = sr[3];
            pacc[0]  += s0.x * hv; pacc[1]  += s0.y * hv;
            pacc[2]  += s0.z * hv; pacc[3]  += s0.w * hv;
            pacc[4]  += s1.x * hv; pacc[5]  += s1.y * hv;
            pacc[6]  += s1.z * hv; pacc[7]  += s1.w * hv;
            pacc[8]  += s2.x * hv; pacc[9]  += s2.y * hv;
            pacc[10] += s2.z * hv; pacc[11] += s2.w * hv;
            pacc[12] += s3.x * hv; pacc[13] += s3.y * hv;
            pacc[14] += s3.z * hv; pacc[15] += s3.w * hv;
        }
        if (cur >= 0) {
            #pragma unroll
            for (int k = 0; k < 16; k++)
                atomicAdd(&d_cluster[((size_t)cur * 16 + k) * HID + tid], pacc[k]);
        }
    }
}

// ---------------- K5: attention readout + folded proj + LN ---------------
__global__ __launch_bounds__(256) void k_readout(
    const float* __restrict__ gamma, const float* __restrict__ beta,
    float* __restrict__ out) {
    int b = blockIdx.x, tid = threadIdx.x, lane = tid & 31, p = tid >> 5;
    __shared__ float cl[16][HID];
    __shared__ float qm[HID][9];
    __shared__ float msh[PH][HID];
    __shared__ float wsh[PH][16];
    __shared__ float red[HID];
    __shared__ float bqs[PH];
    #pragma unroll
    for (int k = 0; k < 16; k++)
        cl[k][tid] = d_cluster[((size_t)b * 16 + k) * HID + tid];
    for (int idx = tid; idx < HID * PH; idx += 256)
        qm[idx >> 3][idx & 7] = d_Qm[idx];
    if (tid < PH) bqs[tid] = d_bq[tid];
    __syncthreads();

    float ml = 0.f;
    for (int k = 0; k < 16; k++) {
        float part = 0.f;
        #pragma unroll
        for (int i = 0; i < 8; i++) { int jj = lane + 32 * i; part += cl[k][jj] * qm[jj][p]; }
        #pragma unroll
        for (int off = 16; off; off >>= 1)
            part += __shfl_xor_sync(0xffffffffu, part, off);
        if (lane == k) ml = part;
    }
    const float scale = 0.17677669529663687f;
    if (lane < 16) {
        float lgv = (ml + bqs[p]) * scale;
        float mx = lgv;
        #pragma unroll
        for (int off = 8; off; off >>= 1)
            mx = fmaxf(mx, __shfl_xor_sync(0xffffu, mx, off, 16));
        float e = expf(lgv - mx), su = e;
        #pragma unroll
        for (int off = 8; off; off >>= 1)
            su += __shfl_xor_sync(0xffffu, su, off, 16);
        wsh[p][lane] = e / su;
    }
    __syncthreads();

    #pragma unroll
    for (int pp = 0; pp < PH; pp++) {
        float a = 0.f;
        #pragma unroll
        for (int k = 0; k < 16; k++) a += wsh[pp][k] * cl[k][tid];
        msh[pp][tid] = a;
    }
    __syncthreads();

    float o = d_bv[tid];
    #pragma unroll 8
    for (int i = 0; i < HID; i++)
        o += msh[p][i] * d_Wcv[(size_t)i * HID + tid];

    red[tid] = o; __syncthreads();
    for (int s = 128; s; s >>= 1) { if (tid < s) red[tid] += red[tid + s]; __syncthreads(); }
    float mu = red[0] * (1.f / HID);
    __syncthreads();
    float dv = o - mu;
    red[tid] = dv * dv; __syncthreads();
    for (int s = 128; s; s >>= 1) { if (tid < s) red[tid] += red[tid + s]; __syncthreads(); }
    float var = red[0] * (1.f / HID);
    out[(size_t)b * HID + tid] = dv * rsqrtf(var + 1e-5f) * gamma[tid] + beta[tid];
}

// ---------------- launch --------------------------------------------------
extern "C" void kernel_launch(void* const* d_in, const int* in_sizes, int n_in,
                              void* d_out, int out_size) {
    const float* h_atom = (const float*)d_in[0];
    const float* c_atom = (const float*)d_in[1];
    const int*   batch  = (const int*)  d_in[2];
    const float* W1 = (const float*)d_in[3];
    const float* b1 = (const float*)d_in[4];
    const float* W2 = (const float*)d_in[5];
    const float* b2 = (const float*)d_in[6];
    const float* A1 = (const float*)d_in[7];
    const float* ab1 = (const float*)d_in[8];
    const float* A2 = (const float*)d_in[9];
    const float* ab2 = (const float*)d_in[10];
    const float* Wc = (const float*)d_in[11];
    const float* bc = (const float*)d_in[12];
    const float* q  = (const float*)d_in[13];
    const float* Wk = (const float*)d_in[14];
    const float* Wv = (const float*)d_in[15];
    const float* gamma = (const float*)d_in[16];
    const float* beta  = (const float*)d_in[17];
    float* out = (float*)d_out;

    int N = in_sizes[0] / HID; if (N > NMAX) N = NMAX;
    int B = out_size / HID;    if (B > BMAX) B = BMAX;

    cudaFuncSetAttribute(k_fused, cudaFuncAttributeMaxDynamicSharedMemorySize, SMEMSZ);

    int gtiles = (N + 63) / 64;
    // observed ncu offset: my index 3 == profiled stream index 5
    k_zero<<<8192, 256>>>();                               // 0
    k_cvtw1<<<384, 256>>>(W1);                             // 1
    k_cvta1<<<256, 256>>>(A1);                             // 2
    k_fused<<<gtiles, 256, SMEMSZ>>>(h_atom, c_atom, batch,
                                     b1, W2, b2, ab1, A2, ab2, N);  // 3
    k_u2<<<256, 256>>>(Wk, q);                             // 4
    k_wcv<<<HID + 1, 256>>>(Wc, Wv, bc);                   // 5
    k_qm<<<HID + 1, 256>>>(Wc, bc);                        // 6
    k_readout<<<B, 256>>>(gamma, beta, out);               // 7
}

// round 17
// speedup vs baseline: 1.1743x; 1.0295x over previous
#include <cuda_runtime.h>
#include <cuda_fp16.h>
#include <math.h>
#include <stdint.h>

#define HID 256
#define CND 128
#define KCL 16
#define PH  8
#define NMAX 262144
#define BMAX 2048

// ---------------- scratch (static device allocations) --------------------
__device__ float d_cluster[(size_t)BMAX * KCL * HID];   // accumulated (zeroed each run)
__device__ float d_u  [HID * PH];
__device__ float d_Qm [HID * PH];
__device__ float d_bq [PH];
__device__ float d_Wcv[HID * HID];
__device__ float d_bv [HID];
__device__ __half d_w1t[256 * 384];
__device__ __half d_a1t[256 * 256];

__device__ __forceinline__ float geluf(float x) {
    return 0.5f * x * (1.0f + erff(x * 0.7071067811865475f));
}
__device__ __forceinline__ uint32_t smem_u32(const void* p) {
    uint32_t a;
    asm("{ .reg .u64 t; cvta.to.shared.u64 t, %1; cvt.u32.u64 %0, t; }"
        : "=r"(a) : "l"(p));
    return a;
}
__device__ __forceinline__ uint32_t f2h2(float lo, float hi) {
    uint32_t r;
    asm("cvt.rn.f16x2.f32 %0, %1, %2;" : "=r"(r) : "f"(hi), "f"(lo));
    return r;
}

#define SW128(o) ((o) ^ (((o) >> 3) & 0x70))

#define LDSM_X4(r, addr) \
    asm volatile("ldmatrix.sync.aligned.m8n8.x4.shared.b16 {%0,%1,%2,%3}, [%4];" \
        : "=r"((r)[0]), "=r"((r)[1]), "=r"((r)[2]), "=r"((r)[3]) : "r"(addr))
#define MMA16816F(c, a, b) \
    asm volatile("mma.sync.aligned.m16n8k16.row.col.f32.f16.f16.f32 " \
        "{%0,%1,%2,%3}, {%4,%5,%6,%7}, {%8,%9}, {%0,%1,%2,%3};" \
        : "+f"((c)[0]), "+f"((c)[1]), "+f"((c)[2]), "+f"((c)[3]) \
        : "r"((a)[0]), "r"((a)[1]), "r"((a)[2]), "r"((a)[3]), \
          "r"((b)[0]), "r"((b)[1]))
#define CP_A16(dst, src) \
    asm volatile("cp.async.cg.shared.global [%0], [%1], 16;" \
        :: "r"(dst), "l"(src) : "memory")
#define CP_A16Z(dst, src, sz) \
    asm volatile("cp.async.cg.shared.global [%0], [%1], 16, %2;" \
        :: "r"(dst), "l"(src), "r"(sz) : "memory")
#define CP_COMMIT() asm volatile("cp.async.commit_group;" ::: "memory")
#define CP_WAIT0()  asm volatile("cp.async.wait_group 0;" ::: "memory")

// smem byte layout per CTA (64-row tile; 2 CTAs/SM)
#define S_BIAS1 0        // 256 f32
#define S_W2    1024     // 256 f32
#define S_AB1   2048     // 256 f32
#define S_AB2   3072     // 16 f32
#define S_ALPHA 3200     // 64 f32
#define S_BIDS  3456     // 64 int (batch ids for pool)
#define S_RED2  3712     // 64*16 f32 = 4096 (logits -> S)
#define AST     8192     // 16KB f32 A staging (aliased as A2 table in epi2)
#define ABF     24576    // 16KB fp16 A (hi only used)
#define BB0     40960    // 32KB fp16 B buf0 | pool h-tile [BB0, BB0+64KB)
#define BB1     73728    // 32KB fp16 B buf1
#define SMEMSZ  106496

// ---------------- tiny prep kernels --------------------------------------
__global__ void k_zero(void) {
    size_t i = (size_t)blockIdx.x * 256 + threadIdx.x;   // 8192*256 float4
    ((float4*)d_cluster)[i] = make_float4(0.f, 0.f, 0.f, 0.f);
}
__global__ void k_cvtw1(const float* __restrict__ W) {
    int t = blockIdx.x, j = threadIdx.x;            // W[384][256] -> WT[256][384]
    d_w1t[(size_t)j * 384 + t] = __float2half_rn(W[(size_t)t * 256 + j]);
}
__global__ void k_cvta1(const float* __restrict__ A) {
    int t = blockIdx.x, j = threadIdx.x;
    d_a1t[(size_t)j * 256 + t] = __float2half_rn(A[(size_t)t * 256 + j]);
}

// ---------------- readout prep (parallel) --------------------------------
__global__ void k_u2(const float* __restrict__ Wk, const float* __restrict__ q) {
    __shared__ float qs[HID];
    int tid = threadIdx.x, t = blockIdx.x;
    qs[tid] = q[tid];
    __syncthreads();
    int lane = tid & 31, p = tid >> 5;
    float v = Wk[(size_t)t * HID + tid] * qs[tid];
    #pragma unroll
    for (int off = 16; off; off >>= 1)
        v += __shfl_xor_sync(0xffffffffu, v, off);
    if (lane == 0) d_u[t * PH + p] = v;
}
__global__ __launch_bounds__(256) void k_wcv(
    const float* __restrict__ Wc, const float* __restrict__ Wv,
    const float* __restrict__ bc) {
    int i = blockIdx.x, j = threadIdx.x;
    float a = 0.f;
    if (i < HID) {
        #pragma unroll 4
        for (int t = 0; t < HID; t++)
            a += Wc[(size_t)i * HID + t] * Wv[(size_t)t * HID + j];
        d_Wcv[(size_t)i * HID + j] = a;
    } else {
        #pragma unroll 4
        for (int t = 0; t < HID; t++)
            a += bc[t] * Wv[(size_t)t * HID + j];
        d_bv[j] = a;
    }
}
__global__ __launch_bounds__(256) void k_qm(
    const float* __restrict__ Wc, const float* __restrict__ bc) {
    __shared__ float wrow[HID];
    int i = blockIdx.x, tid = threadIdx.x;
    wrow[tid] = (i < HID) ? Wc[(size_t)i * HID + tid] : bc[tid];
    __syncthreads();
    int p = tid >> 5, lane = tid & 31;
    float v = 0.f;
    #pragma unroll
    for (int t = 0; t < 8; t++) {
        int idx = lane + 32 * t;
        v += wrow[idx] * d_u[idx * PH + p];
    }
    #pragma unroll
    for (int off = 16; off; off >>= 1)
        v += __shfl_xor_sync(0xffffffffu, v, off);
    if (lane == 0) { if (i < HID) d_Qm[i * PH + p] = v; else d_bq[p] = v; }
}

// ======================= fused atom kernel (fp16, persistent) =============
__device__ __forceinline__ void mma_block(uint32_t abf, uint32_t bbase,
                                          int lane, int wm, int wn,
                                          float acc[2][8][4]) {
    #pragma unroll
    for (int ks = 0; ks < 4; ks++) {
        int kb = ks * 32;
        uint32_t ah[2][4];
        #pragma unroll
        for (int mt = 0; mt < 2; mt++) {
            int mb = wm * 32 + mt * 16 + (lane & 7) + ((lane & 8) ? 8 : 0);
            uint32_t ao = SW128((uint32_t)(mb * 128 + kb + ((lane & 16) ? 16 : 0)));
            LDSM_X4(ah[mt], abf + ao);
        }
        #pragma unroll
        for (int np = 0; np < 4; np++) {
            int nb = wn * 64 + (np * 2 + ((lane >> 4) & 1)) * 8 + (lane & 7);
            uint32_t bo = SW128((uint32_t)(nb * 128 + kb + ((lane & 8) ? 16 : 0)));
            uint32_t bh[4];
            LDSM_X4(bh, bbase + bo);
            MMA16816F(acc[0][2*np],   ah[0], bh);
            MMA16816F(acc[1][2*np],   ah[1], bh);
            MMA16816F(acc[0][2*np+1], ah[0], bh + 2);
            MMA16816F(acc[1][2*np+1], ah[1], bh + 2);
        }
    }
}

__global__ void __launch_bounds__(256, 2) k_fused(
    const float* __restrict__ h, const float* __restrict__ c,
    const int* __restrict__ batch,
    const float* __restrict__ b1, const float* __restrict__ W2,
    const float* __restrict__ b2, const float* __restrict__ ab1,
    const float* __restrict__ A2, const float* __restrict__ ab2,
    int gtiles, int N) {
    extern __shared__ __align__(1024) char smem[];
    uint32_t sb = smem_u32(smem);
    int tid = threadIdx.x, lane = tid & 31, wid = tid >> 5;
    int wm = wid & 1, wn = wid >> 1;     // 2 x 4 warp grid: 64 rows x 256 cols
    int r0;

    float* bias1 = (float*)(smem + S_BIAS1);
    float* w2s   = (float*)(smem + S_W2);
    float* ab1s  = (float*)(smem + S_AB1);
    float* ab2s  = (float*)(smem + S_AB2);
    float* alpha = (float*)(smem + S_ALPHA);
    int*   bids  = (int*)  (smem + S_BIDS);
    float* red2  = (float*)(smem + S_RED2);

    // constants: once per CTA
    bias1[tid] = b1[tid];
    w2s[tid]   = W2[tid];
    ab1s[tid]  = ab1[tid];
    if (tid < 16) ab2s[tid] = ab2[tid];
    float b2v = b2[0];

    // per-thread load coordinates
    int a_row = tid >> 4, a_c4 = (tid & 15) * 4;
    int b_row = tid >> 3, b_u8 = (tid & 7) * 8;

    auto issueA = [&](const float* src1, int ch) {
        int kt = ch * 64;
        const float* src; int stride, cb;
        if (kt < 256) { src = src1; stride = 256; cb = kt; }
        else          { src = c;    stride = 128; cb = kt - 256; }
        #pragma unroll
        for (int i = 0; i < 4; i++) {
            int idx = tid + i * 256;
            int row = a_row + i * 16;
            int gr = r0 + row;
            const float* sp = src + (size_t)gr * stride + cb + a_c4;
            int sz = (gr < N) ? 16 : 0;
            CP_A16Z(sb + AST + idx * 16, sp, sz);
        }
    };
    auto issueB = [&](const __half* Bt, int stride, int ch, uint32_t bbuf) {
        int kt = ch * 64;
        #pragma unroll
        for (int i = 0; i < 8; i++) {
            int row = b_row + i * 32;
            uint32_t off = SW128((uint32_t)(row * 128 + b_u8 * 2));
            CP_A16(sb + bbuf + off, Bt + (size_t)row * stride + kt + b_u8);
        }
    };
    auto splitA = [&]() {                // hi only, packed f16x2 converts
        #pragma unroll
        for (int i = 0; i < 4; i++) {
            int idx = tid + i * 256;
            int row = a_row + i * 16;
            float4 v = *(const float4*)(smem + AST + idx * 16);
            uint32_t p01 = f2h2(v.x, v.y);
            uint32_t p23 = f2h2(v.z, v.w);
            uint32_t off = SW128((uint32_t)(row * 128 + a_c4 * 2));
            *(uint2*)(smem + ABF + off) = make_uint2(p01, p23);
        }
    };

    for (int tile = blockIdx.x; tile < gtiles; tile += gridDim.x) {
        r0 = tile * 64;
        if (tid < 64) alpha[tid] = 0.f;
        for (int i = tid; i < 64 * 16; i += 256) red2[i] = 0.f;

        float acc[2][8][4];
        #pragma unroll
        for (int a = 0; a < 2; a++)
            #pragma unroll
            for (int b = 0; b < 8; b++)
                #pragma unroll
                for (int e = 0; e < 4; e++) acc[a][b][e] = 0.f;

        // =================== phase 1: D1 = [h|c] @ W1 ====================
        issueA(h, 0);
        issueB(d_w1t, 384, 0, BB0);
        CP_COMMIT();
        for (int ch = 0; ch < 6; ch++) {
            uint32_t bbuf = (ch & 1) ? BB1 : BB0;
            CP_WAIT0();
            __syncthreads();
            splitA();
            if (ch < 5) {
                issueA(h, ch + 1);
                issueB(d_w1t, 384, ch + 1, (ch & 1) ? BB0 : BB1);
            } else {
                issueA(h, 0);               // phase-2 chunk0 (alpha-independent)
                issueB(d_a1t, 256, 0, BB0);
            }
            CP_COMMIT();
            __syncthreads();
            mma_block(sb + ABF, sb + bbuf, lane, wm, wn, acc);
        }
        // =================== epilogue 1: gate -> alpha ===================
        #pragma unroll
        for (int mt = 0; mt < 2; mt++) {
            float s0 = 0.f, s1 = 0.f;
            #pragma unroll
            for (int nt = 0; nt < 8; nt++) {
                int n = wn * 64 + nt * 8 + (lane & 3) * 2;
                float b0v = bias1[n], b1v = bias1[n + 1];
                float w0 = w2s[n], w1v = w2s[n + 1];
                s0 += geluf(acc[mt][nt][0] + b0v) * w0 + geluf(acc[mt][nt][1] + b1v) * w1v;
                s1 += geluf(acc[mt][nt][2] + b0v) * w0 + geluf(acc[mt][nt][3] + b1v) * w1v;
            }
            s0 += __shfl_xor_sync(0xffffffffu, s0, 1);
            s0 += __shfl_xor_sync(0xffffffffu, s0, 2);
            s1 += __shfl_xor_sync(0xffffffffu, s1, 1);
            s1 += __shfl_xor_sync(0xffffffffu, s1, 2);
            if ((lane & 3) == 0) {
                int r = wm * 32 + mt * 16 + (lane >> 2);
                atomicAdd(&alpha[r], s0);
                atomicAdd(&alpha[r + 8], s1);
            }
        }
        __syncthreads();
        if (tid < 64) alpha[tid] = 1.f / (1.f + expf(-(alpha[tid] + b2v)));
        // =================== phase 2: E = h @ A1 =========================
        #pragma unroll
        for (int a = 0; a < 2; a++)
            #pragma unroll
            for (int b = 0; b < 8; b++)
                #pragma unroll
                for (int e = 0; e < 4; e++) acc[a][b][e] = 0.f;

        for (int ch = 0; ch < 4; ch++) {
            uint32_t bbuf = (ch & 1) ? BB1 : BB0;
            CP_WAIT0();
            __syncthreads();
            splitA();
            if (ch < 3) {
                issueA(h, ch + 1);
                issueB(d_a1t, 256, ch + 1, (ch & 1) ? BB0 : BB1);
            }
            CP_COMMIT();
            __syncthreads();
            mma_block(sb + ABF, sb + bbuf, lane, wm, wn, acc);
        }
        __syncthreads();   // all warps done reading BB0/BB1
        // prefetch full h tile [64 x 256] f32 into BB0..+64KB (overlaps epi2)
        #pragma unroll
        for (int i = 0; i < 16; i++) {
            int idx = tid + i * 256;
            int row = idx >> 6, c4 = (idx & 63) * 4;
            int gr = r0 + row;
            const float* sp = h + (size_t)gr * 256 + c4;
            int sz = (gr < N) ? 16 : 0;
            CP_A16Z(sb + BB0 + idx * 16, sp, sz);
        }
        CP_COMMIT();
        {
            float* a2s = (float*)(smem + AST);
            for (int i = tid; i < 256 * 16; i += 256) a2s[i] = A2[i];
        }
        if (tid < 64) {
            int gr = r0 + tid;
            bids[tid] = (gr < N) ? batch[gr] : -1;
        }
        __syncthreads();
        // ============ epilogue 2: alpha-scale + @A2 -> logits ============
        {
            const float* a2s = (const float*)(smem + AST);
            #pragma unroll
            for (int mt = 0; mt < 2; mt++) {
                float l0[16], l1[16];
                #pragma unroll
                for (int k = 0; k < 16; k++) { l0[k] = 0.f; l1[k] = 0.f; }
                float ar0 = alpha[wm * 32 + mt * 16 + (lane >> 2)];
                float ar1 = alpha[wm * 32 + mt * 16 + (lane >> 2) + 8];
                #pragma unroll
                for (int nt = 0; nt < 8; nt++) {
                    int n = wn * 64 + nt * 8 + (lane & 3) * 2;
                    #pragma unroll
                    for (int e = 0; e < 4; e++) {
                        int col = n + (e & 1);
                        float av = (e < 2) ? ar0 : ar1;
                        float v = geluf(av * acc[mt][nt][e] + ab1s[col]);
                        const float* ar = &a2s[col * 16];
                        float* dst = (e < 2) ? l0 : l1;
                        #pragma unroll
                        for (int k = 0; k < 16; k++) dst[k] += v * ar[k];
                    }
                }
                #pragma unroll
                for (int k = 0; k < 16; k++) {
                    l0[k] += __shfl_xor_sync(0xffffffffu, l0[k], 1);
                    l0[k] += __shfl_xor_sync(0xffffffffu, l0[k], 2);
                    l1[k] += __shfl_xor_sync(0xffffffffu, l1[k], 1);
                    l1[k] += __shfl_xor_sync(0xffffffffu, l1[k], 2);
                }
                if ((lane & 3) == 0) {
                    int r = wm * 32 + mt * 16 + (lane >> 2);
                    #pragma unroll
                    for (int k = 0; k < 16; k++) {
                        atomicAdd(&red2[r * 16 + k], l0[k]);
                        atomicAdd(&red2[(r + 8) * 16 + k], l1[k]);
                    }
                }
            }
        }
        __syncthreads();
        // softmax * alpha -> S (in red2)
        if (tid < 64) {
            int gr = r0 + tid;
            if (gr < N) {
                float l[16], mx = -1e30f;
                #pragma unroll
                for (int k = 0; k < 16; k++) {
                    l[k] = red2[tid * 16 + k] + ab2s[k];
                    mx = fmaxf(mx, l[k]);
                }
                float s = 0.f;
                #pragma unroll
                for (int k = 0; k < 16; k++) { l[k] = expf(l[k] - mx); s += l[k]; }
                float inv = alpha[tid] / s;
                #pragma unroll
                for (int k = 0; k < 16; k++) red2[tid * 16 + k] = l[k] * inv;
            } else {
                #pragma unroll
                for (int k = 0; k < 16; k++) red2[tid * 16 + k] = 0.f;
            }
        }
        CP_WAIT0();          // h tile landed
        __syncthreads();
        // ======== fused segment pool: d_cluster[b,k,j] += S[n,k]*h[n,j] ==
        {
            const float* hsm = (const float*)(smem + BB0);
            float pacc[16];
            #pragma unroll
            for (int k = 0; k < 16; k++) pacc[k] = 0.f;
            int cur = bids[0];
            for (int n = 0; n < 64; n++) {
                int bn = bids[n];
                if (bn != cur) {
                    if (cur >= 0) {
                        #pragma unroll
                        for (int k = 0; k < 16; k++)
                            atomicAdd(&d_cluster[((size_t)cur * 16 + k) * HID + tid], pacc[k]);
                    }
                    #pragma unroll
                    for (int k = 0; k < 16; k++) pacc[k] = 0.f;
                    cur = bn;
                }
                float hv = hsm[n * HID + tid];
                const float4* sr = (const float4*)&red2[n * 16];
                float4 s0 = sr[0], s1 = sr[1], s2 = sr[2], s3 = sr[3];
                pacc[0]  += s0.x * hv; pacc[1]  += s0.y * hv;
                pacc[2]  += s0.z * hv; pacc[3]  += s0.w * hv;
                pacc[4]  += s1.x * hv; pacc[5]  += s1.y * hv;
                pacc[6]  += s1.z * hv; pacc[7]  += s1.w * hv;
                pacc[8]  += s2.x * hv; pacc[9]  += s2.y * hv;
                pacc[10] += s2.z * hv; pacc[11] += s2.w * hv;
                pacc[12] += s3.x * hv; pacc[13] += s3.y * hv;
                pacc[14] += s3.z * hv; pacc[15] += s3.w * hv;
            }
            if (cur >= 0) {
                #pragma unroll
                for (int k = 0; k < 16; k++)
                    atomicAdd(&d_cluster[((size_t)cur * 16 + k) * HID + tid], pacc[k]);
            }
        }
        __syncthreads();     // BB0 (h tile) fully consumed before next tile
    }
}

// ---------------- K5: attention readout + folded proj + LN ---------------
__global__ __launch_bounds__(256) void k_readout(
    const float* __restrict__ gamma, const float* __restrict__ beta,
    float* __restrict__ out) {
    int b = blockIdx.x, tid = threadIdx.x, lane = tid & 31, p = tid >> 5;
    __shared__ float cl[16][HID];
    __shared__ float qm[HID][9];
    __shared__ float msh[PH][HID];
    __shared__ float wsh[PH][16];
    __shared__ float red[HID];
    __shared__ float bqs[PH];
    #pragma unroll
    for (int k = 0; k < 16; k++)
        cl[k][tid] = d_cluster[((size_t)b * 16 + k) * HID + tid];
    for (int idx = tid; idx < HID * PH; idx += 256)
        qm[idx >> 3][idx & 7] = d_Qm[idx];
    if (tid < PH) bqs[tid] = d_bq[tid];
    __syncthreads();

    float ml = 0.f;
    for (int k = 0; k < 16; k++) {
        float part = 0.f;
        #pragma unroll
        for (int i = 0; i < 8; i++) { int jj = lane + 32 * i; part += cl[k][jj] * qm[jj][p]; }
        #pragma unroll
        for (int off = 16; off; off >>= 1)
            part += __shfl_xor_sync(0xffffffffu, part, off);
        if (lane == k) ml = part;
    }
    const float scale = 0.17677669529663687f;
    if (lane < 16) {
        float lgv = (ml + bqs[p]) * scale;
        float mx = lgv;
        #pragma unroll
        for (int off = 8; off; off >>= 1)
            mx = fmaxf(mx, __shfl_xor_sync(0xffffu, mx, off, 16));
        float e = expf(lgv - mx), su = e;
        #pragma unroll
        for (int off = 8; off; off >>= 1)
            su += __shfl_xor_sync(0xffffu, su, off, 16);
        wsh[p][lane] = e / su;
    }
    __syncthreads();

    #pragma unroll
    for (int pp = 0; pp < PH; pp++) {
        float a = 0.f;
        #pragma unroll
        for (int k = 0; k < 16; k++) a += wsh[pp][k] * cl[k][tid];
        msh[pp][tid] = a;
    }
    __syncthreads();

    float o = d_bv[tid];
    #pragma unroll 8
    for (int i = 0; i < HID; i++)
        o += msh[p][i] * d_Wcv[(size_t)i * HID + tid];

    red[tid] = o; __syncthreads();
    for (int s = 128; s; s >>= 1) { if (tid < s) red[tid] += red[tid + s]; __syncthreads(); }
    float mu = red[0] * (1.f / HID);
    __syncthreads();
    float dv = o - mu;
    red[tid] = dv * dv; __syncthreads();
    for (int s = 128; s; s >>= 1) { if (tid < s) red[tid] += red[tid + s]; __syncthreads(); }
    float var = red[0] * (1.f / HID);
    out[(size_t)b * HID + tid] = dv * rsqrtf(var + 1e-5f) * gamma[tid] + beta[tid];
}

// ---------------- launch --------------------------------------------------
extern "C" void kernel_launch(void* const* d_in, const int* in_sizes, int n_in,
                              void* d_out, int out_size) {
    const float* h_atom = (const float*)d_in[0];
    const float* c_atom = (const float*)d_in[1];
    const int*   batch  = (const int*)  d_in[2];
    const float* W1 = (const float*)d_in[3];
    const float* b1 = (const float*)d_in[4];
    const float* W2 = (const float*)d_in[5];
    const float* b2 = (const float*)d_in[6];
    const float* A1 = (const float*)d_in[7];
    const float* ab1 = (const float*)d_in[8];
    const float* A2 = (const float*)d_in[9];
    const float* ab2 = (const float*)d_in[10];
    const float* Wc = (const float*)d_in[11];
    const float* bc = (const float*)d_in[12];
    const float* q  = (const float*)d_in[13];
    const float* Wk = (const float*)d_in[14];
    const float* Wv = (const float*)d_in[15];
    const float* gamma = (const float*)d_in[16];
    const float* beta  = (const float*)d_in[17];
    float* out = (float*)d_out;

    int N = in_sizes[0] / HID; if (N > NMAX) N = NMAX;
    int B = out_size / HID;    if (B > BMAX) B = BMAX;

    cudaFuncSetAttribute(k_fused, cudaFuncAttributeMaxDynamicSharedMemorySize, SMEMSZ);

    int gtiles = (N + 63) / 64;
    int pgrid = gtiles < 296 ? gtiles : 296;
    // observed ncu offset: my index 3 == profiled stream index 5
    k_zero<<<8192, 256>>>();                               // 0
    k_cvtw1<<<384, 256>>>(W1);                             // 1
    k_cvta1<<<256, 256>>>(A1);                             // 2
    k_fused<<<pgrid, 256, SMEMSZ>>>(h_atom, c_atom, batch,
                                    b1, W2, b2, ab1, A2, ab2, gtiles, N);  // 3
    k_u2<<<256, 256>>>(Wk, q);                             // 4
    k_wcv<<<HID + 1, 256>>>(Wc, Wv, bc);                   // 5
    k_qm<<<HID + 1, 256>>>(Wc, bc);                        // 6
    k_readout<<<B, 256>>>(gamma, beta, out);               // 7
}